// round 3
// baseline (speedup 1.0000x reference)
#include <cuda_runtime.h>

#define HD 64
#define NMAX 100000
#define GMAX 32768

// Scratch (no allocations allowed -> __device__ globals)
__device__ float g_A[NMAX * HD];     // per-node: msg_b1' + silu(n1) @ Wf2   (msg layer1 source part, fully folded)
__device__ float g_C[NMAX * HD];     // per-node: edge_b1 + pos @ edge_w1[0:3]
__device__ float g_Wf[HD * HD];      // edge_w2 @ msg_w1[64:128]
__device__ float g_Wf2[HD * HD];     // node_w2 @ msg_w1[0:64]
__device__ float g_cA[HD];           // msg_b1 + node_b2@msg_w1_top + edge_b2@msg_w1_bot
__device__ float g_sums[GMAX * HD];
__device__ float g_cnt[GMAX];

__device__ __forceinline__ float silu_f(float x) {
    return x * (1.0f / (1.0f + __expf(-x)));
}

// acc[j] += v[k] * W[k][j], W in shared as float4 rows (64x64)
__device__ __forceinline__ void gemv64(const float* v, const float4* sW, float* acc) {
#pragma unroll
    for (int k = 0; k < 64; k++) {
        float vk = v[k];
#pragma unroll
        for (int j4 = 0; j4 < 16; j4++) {
            float4 w = sW[k * 16 + j4];
            acc[4 * j4 + 0] = fmaf(vk, w.x, acc[4 * j4 + 0]);
            acc[4 * j4 + 1] = fmaf(vk, w.y, acc[4 * j4 + 1]);
            acc[4 * j4 + 2] = fmaf(vk, w.z, acc[4 * j4 + 2]);
            acc[4 * j4 + 3] = fmaf(vk, w.w, acc[4 * j4 + 3]);
        }
    }
}

// ---------------------------------------------------------------------------
// Zero the scatter buffers
// ---------------------------------------------------------------------------
__global__ void zero_kernel(int G) {
    int total4 = G * 16;  // G*64/4
    for (int i = blockIdx.x * blockDim.x + threadIdx.x; i < total4;
         i += gridDim.x * blockDim.x)
        reinterpret_cast<float4*>(g_sums)[i] = make_float4(0.f, 0.f, 0.f, 0.f);
    for (int i = blockIdx.x * blockDim.x + threadIdx.x; i < G;
         i += gridDim.x * blockDim.x)
        g_cnt[i] = 0.f;
}

// ---------------------------------------------------------------------------
// Fold weight products (tiny, one block)
//   Wf2 = node_w2 @ msg_w1_top      Wf = edge_w2 @ msg_w1_bot
//   cA  = msg_b1 + node_b2 @ msg_w1_top + edge_b2 @ msg_w1_bot
// ---------------------------------------------------------------------------
__global__ void fold_kernel(const float* __restrict__ node_w2,
                            const float* __restrict__ node_b2,
                            const float* __restrict__ edge_w2,
                            const float* __restrict__ edge_b2,
                            const float* __restrict__ msg_w1,
                            const float* __restrict__ msg_b1) {
    int j = threadIdx.x & 63;
    int q = threadIdx.x >> 6;  // 0..3
    for (int i = q * 16; i < q * 16 + 16; i++) {
        float a = 0.f, b = 0.f;
        for (int k = 0; k < 64; k++) {
            a = fmaf(node_w2[i * 64 + k], msg_w1[k * 64 + j], a);
            b = fmaf(edge_w2[i * 64 + k], msg_w1[(64 + k) * 64 + j], b);
        }
        g_Wf2[i * 64 + j] = a;
        g_Wf[i * 64 + j]  = b;
    }
    if (q == 0) {
        float c = msg_b1[j];
        for (int k = 0; k < 64; k++) {
            c = fmaf(node_b2[k], msg_w1[k * 64 + j], c);
            c = fmaf(edge_b2[k], msg_w1[(64 + k) * 64 + j], c);
        }
        g_cA[j] = c;
    }
}

// ---------------------------------------------------------------------------
// Per-node precompute: A'[n] = cA + silu(x@node_w1 + node_b1) @ Wf2
//                      C[n]  = edge_b1 + pos[n] @ edge_w1[0:3]
// ---------------------------------------------------------------------------
__global__ __launch_bounds__(128) void node_kernel(
    const float* __restrict__ x, const float* __restrict__ pos,
    const float* __restrict__ node_w1, const float* __restrict__ node_b1,
    const float* __restrict__ edge_w1, const float* __restrict__ edge_b1,
    int N) {
    __shared__ float4 sW1[HD * 16];
    __shared__ float4 sWf2[HD * 16];
    __shared__ float  sEw[3 * 64];
    __shared__ float  sB1[64], sCA[64], sEb[64];

    for (int i = threadIdx.x; i < HD * 16; i += blockDim.x) {
        sW1[i]  = reinterpret_cast<const float4*>(node_w1)[i];
        sWf2[i] = reinterpret_cast<const float4*>(g_Wf2)[i];
    }
    for (int i = threadIdx.x; i < 192; i += blockDim.x) sEw[i] = edge_w1[i];
    if (threadIdx.x < 64) {
        sB1[threadIdx.x] = node_b1[threadIdx.x];
        sCA[threadIdx.x] = g_cA[threadIdx.x];
        sEb[threadIdx.x] = edge_b1[threadIdx.x];
    }
    __syncthreads();

    for (int n = blockIdx.x * blockDim.x + threadIdx.x; n < N;
         n += gridDim.x * blockDim.x) {
        float acc[64];
#pragma unroll
        for (int j = 0; j < 64; j++) acc[j] = sB1[j];

        const float4* xr = reinterpret_cast<const float4*>(x + (size_t)n * 64);
#pragma unroll
        for (int k4 = 0; k4 < 16; k4++) {
            float4 xv = __ldg(xr + k4);
            float xs[4] = {xv.x, xv.y, xv.z, xv.w};
#pragma unroll
            for (int kk = 0; kk < 4; kk++) {
                float vk = xs[kk];
                int k = 4 * k4 + kk;
#pragma unroll
                for (int j4 = 0; j4 < 16; j4++) {
                    float4 w = sW1[k * 16 + j4];
                    acc[4 * j4 + 0] = fmaf(vk, w.x, acc[4 * j4 + 0]);
                    acc[4 * j4 + 1] = fmaf(vk, w.y, acc[4 * j4 + 1]);
                    acc[4 * j4 + 2] = fmaf(vk, w.z, acc[4 * j4 + 2]);
                    acc[4 * j4 + 3] = fmaf(vk, w.w, acc[4 * j4 + 3]);
                }
            }
        }

        float v[64];
#pragma unroll
        for (int j = 0; j < 64; j++) v[j] = silu_f(acc[j]);

        float acc2[64];
#pragma unroll
        for (int j = 0; j < 64; j++) acc2[j] = sCA[j];
        gemv64(v, sWf2, acc2);

        float4* Arow = reinterpret_cast<float4*>(g_A + (size_t)n * 64);
#pragma unroll
        for (int j4 = 0; j4 < 16; j4++)
            Arow[j4] = make_float4(acc2[4 * j4 + 0], acc2[4 * j4 + 1],
                                   acc2[4 * j4 + 2], acc2[4 * j4 + 3]);

        float px = pos[n * 3 + 0], py = pos[n * 3 + 1], pz = pos[n * 3 + 2];
        float4* Crow = reinterpret_cast<float4*>(g_C + (size_t)n * 64);
#pragma unroll
        for (int j4 = 0; j4 < 16; j4++) {
            float c[4];
#pragma unroll
            for (int kk = 0; kk < 4; kk++) {
                int j = 4 * j4 + kk;
                c[kk] = sEb[j];
                c[kk] = fmaf(px, sEw[j], c[kk]);
                c[kk] = fmaf(py, sEw[64 + j], c[kk]);
                c[kk] = fmaf(pz, sEw[128 + j], c[kk]);
            }
            Crow[j4] = make_float4(c[0], c[1], c[2], c[3]);
        }
    }
}

// ---------------------------------------------------------------------------
// Per-edge: t1 = C[s] + trel@edge_w1[3:6]; m1 = A'[s] + silu(t1)@Wf;
//           msg = msg_b2 + silu(m1)@msg_w2; atomic scatter into g_sums/g_cnt
// ---------------------------------------------------------------------------
__global__ __launch_bounds__(128) void edge_kernel(
    const int* __restrict__ src, const int* __restrict__ tgt,
    const float* __restrict__ node_pos, const float* __restrict__ grid_pos,
    const float* __restrict__ orient,
    const float* __restrict__ edge_w1,
    const float* __restrict__ msg_w2, const float* __restrict__ msg_b2,
    int E, int G) {
    __shared__ float4 sWf[HD * 16];
    __shared__ float4 sW2[HD * 16];
    __shared__ float  sEw[3 * 64];
    __shared__ float  sB2[64];

    for (int i = threadIdx.x; i < HD * 16; i += blockDim.x) {
        sWf[i] = reinterpret_cast<const float4*>(g_Wf)[i];
        sW2[i] = reinterpret_cast<const float4*>(msg_w2)[i];
    }
    for (int i = threadIdx.x; i < 192; i += blockDim.x) sEw[i] = edge_w1[192 + i];
    if (threadIdx.x < 64) sB2[threadIdx.x] = msg_b2[threadIdx.x];
    __syncthreads();

    for (int e = blockIdx.x * blockDim.x + threadIdx.x; e < E;
         e += gridDim.x * blockDim.x) {
        int s = src[e];
        int t = tgt[e];
        if (t < 0 || t >= G) continue;

        float px = node_pos[s * 3 + 0], py = node_pos[s * 3 + 1], pz = node_pos[s * 3 + 2];
        float rx = grid_pos[t * 3 + 0] - px;
        float ry = grid_pos[t * 3 + 1] - py;
        float rz = grid_pos[t * 3 + 2] - pz;
        const float* R = orient + (size_t)s * 9;
        float t0 = rx * R[0] + ry * R[3] + rz * R[6];
        float t1 = rx * R[1] + ry * R[4] + rz * R[7];
        float t2 = rx * R[2] + ry * R[5] + rz * R[8];

        // t1 stage + silu
        float v[64];
        const float4* Crow = reinterpret_cast<const float4*>(g_C + (size_t)s * 64);
#pragma unroll
        for (int j4 = 0; j4 < 16; j4++) {
            float4 c = __ldg(Crow + j4);
            float cv[4] = {c.x, c.y, c.z, c.w};
#pragma unroll
            for (int kk = 0; kk < 4; kk++) {
                int j = 4 * j4 + kk;
                float a = cv[kk];
                a = fmaf(t0, sEw[j], a);
                a = fmaf(t1, sEw[64 + j], a);
                a = fmaf(t2, sEw[128 + j], a);
                v[j] = silu_f(a);
            }
        }

        // m1 = A'[s] + v @ Wf
        float acc[64];
        const float4* Arow = reinterpret_cast<const float4*>(g_A + (size_t)s * 64);
#pragma unroll
        for (int j4 = 0; j4 < 16; j4++) {
            float4 a = __ldg(Arow + j4);
            acc[4 * j4 + 0] = a.x; acc[4 * j4 + 1] = a.y;
            acc[4 * j4 + 2] = a.z; acc[4 * j4 + 3] = a.w;
        }
        gemv64(v, sWf, acc);

#pragma unroll
        for (int j = 0; j < 64; j++) v[j] = silu_f(acc[j]);

        // msg = msg_b2 + v @ msg_w2
#pragma unroll
        for (int j = 0; j < 64; j++) acc[j] = sB2[j];
        gemv64(v, sW2, acc);

        float* srow = g_sums + (size_t)t * 64;
#pragma unroll
        for (int j = 0; j < 64; j++) atomicAdd(srow + j, acc[j]);
        atomicAdd(&g_cnt[t], 1.0f);
    }
}

// ---------------------------------------------------------------------------
// Finalize: grid_feat = sums / max(cnt,1); out = silu(gf@upd_w1+b1)@upd_w2+b2
// ---------------------------------------------------------------------------
__global__ __launch_bounds__(128) void final_kernel(
    const float* __restrict__ upd_w1, const float* __restrict__ upd_b1,
    const float* __restrict__ upd_w2, const float* __restrict__ upd_b2,
    float* __restrict__ out, int G) {
    __shared__ float4 sU1[HD * 16];
    __shared__ float4 sU2[HD * 16];
    __shared__ float  sB1[64], sB2[64];

    for (int i = threadIdx.x; i < HD * 16; i += blockDim.x) {
        sU1[i] = reinterpret_cast<const float4*>(upd_w1)[i];
        sU2[i] = reinterpret_cast<const float4*>(upd_w2)[i];
    }
    if (threadIdx.x < 64) {
        sB1[threadIdx.x] = upd_b1[threadIdx.x];
        sB2[threadIdx.x] = upd_b2[threadIdx.x];
    }
    __syncthreads();

    for (int g = blockIdx.x * blockDim.x + threadIdx.x; g < G;
         g += gridDim.x * blockDim.x) {
        float cnt = g_cnt[g];
        float inv = 1.0f / fmaxf(cnt, 1.0f);

        float v[64];
        const float4* Srow = reinterpret_cast<const float4*>(g_sums + (size_t)g * 64);
#pragma unroll
        for (int j4 = 0; j4 < 16; j4++) {
            float4 sv = Srow[j4];
            v[4 * j4 + 0] = sv.x * inv; v[4 * j4 + 1] = sv.y * inv;
            v[4 * j4 + 2] = sv.z * inv; v[4 * j4 + 3] = sv.w * inv;
        }

        float acc[64];
#pragma unroll
        for (int j = 0; j < 64; j++) acc[j] = sB1[j];
        gemv64(v, sU1, acc);

#pragma unroll
        for (int j = 0; j < 64; j++) v[j] = silu_f(acc[j]);

#pragma unroll
        for (int j = 0; j < 64; j++) acc[j] = sB2[j];
        gemv64(v, sU2, acc);

        float4* orow = reinterpret_cast<float4*>(out + (size_t)g * 64);
#pragma unroll
        for (int j4 = 0; j4 < 16; j4++)
            orow[j4] = make_float4(acc[4 * j4 + 0], acc[4 * j4 + 1],
                                   acc[4 * j4 + 2], acc[4 * j4 + 3]);
    }
}

// ---------------------------------------------------------------------------
extern "C" void kernel_launch(void* const* d_in, const int* in_sizes, int n_in,
                              void* d_out, int out_size) {
    const float* node_features = (const float*)d_in[0];
    const float* node_pos      = (const float*)d_in[1];
    const float* grid_pos      = (const float*)d_in[2];
    const float* orientations  = (const float*)d_in[3];
    const int*   edge_index    = (const int*)d_in[4];
    const float* node_w1 = (const float*)d_in[5];
    const float* node_b1 = (const float*)d_in[6];
    const float* node_w2 = (const float*)d_in[7];
    const float* node_b2 = (const float*)d_in[8];
    const float* edge_w1 = (const float*)d_in[9];
    const float* edge_b1 = (const float*)d_in[10];
    const float* edge_w2 = (const float*)d_in[11];
    const float* edge_b2 = (const float*)d_in[12];
    const float* msg_w1  = (const float*)d_in[13];
    const float* msg_b1  = (const float*)d_in[14];
    const float* msg_w2  = (const float*)d_in[15];
    const float* msg_b2  = (const float*)d_in[16];
    const float* upd_w1  = (const float*)d_in[17];
    const float* upd_b1  = (const float*)d_in[18];
    const float* upd_w2  = (const float*)d_in[19];
    const float* upd_b2  = (const float*)d_in[20];

    int N = in_sizes[0] / 64;
    int G = in_sizes[2] / 3;
    int E = in_sizes[4] / 2;
    const int* src = edge_index;
    const int* tgt = edge_index + E;

    zero_kernel<<<256, 256>>>(G);
    fold_kernel<<<1, 256>>>(node_w2, node_b2, edge_w2, edge_b2, msg_w1, msg_b1);
    node_kernel<<<(N + 127) / 128, 128>>>(node_features, node_pos,
                                          node_w1, node_b1, edge_w1, edge_b1, N);
    int nb = 1480;
    if ((long long)nb * 128 > E) nb = (E + 127) / 128;
    edge_kernel<<<nb, 128>>>(src, tgt, node_pos, grid_pos, orientations,
                             edge_w1, msg_w2, msg_b2, E, G);
    final_kernel<<<(G + 127) / 128, 128>>>(upd_w1, upd_b1, upd_w2, upd_b2,
                                           (float*)d_out, G);
}

// round 5
// speedup vs baseline: 2.3316x; 2.3316x over previous
#include <cuda_runtime.h>

#define HD 64
#define NMAX 100000
#define GMAX 32768

// Scratch (no allocations allowed -> __device__ globals)
__device__ float g_A[NMAX * HD];     // per-node: cA + silu(n1) @ Wf2  (pre-silu m1 source part)
__device__ float g_C[NMAX * HD];     // per-node: edge_b1 + pos @ edge_w1[0:3]
__device__ float g_Wf[HD * HD];      // edge_w2 @ msg_w1[64:128]
__device__ float g_Wf2[HD * HD];     // node_w2 @ msg_w1[0:64]
__device__ float g_cA[HD];           // msg_b1 + node_b2@msg_w1_top + edge_b2@msg_w1_bot
__device__ float g_sums[GMAX * HD];  // sum of silu(m1) per grid cell (msg_w2 folded out)
__device__ float g_cnt[GMAX];

__device__ __forceinline__ float silu_f(float x) {
    return __fdividef(x, 1.0f + __expf(-x));
}

__device__ __forceinline__ unsigned long long pack2(float x, float y) {
    unsigned long long r;
    asm("mov.b64 %0, {%1, %2};" : "=l"(r) : "f"(x), "f"(y));
    return r;
}
__device__ __forceinline__ void unpack2(unsigned long long v, float& x, float& y) {
    asm("mov.b64 {%0, %1}, %2;" : "=f"(x), "=f"(y) : "l"(v));
}
__device__ __forceinline__ unsigned long long bcast2(float x) {
    unsigned long long r;
    asm("mov.b64 %0, {%1, %1};" : "=l"(r) : "f"(x));
    return r;
}
__device__ __forceinline__ void fma2(unsigned long long& acc, unsigned long long a,
                                     unsigned long long b) {
    asm("fma.rn.f32x2 %0, %1, %2, %0;" : "+l"(acc) : "l"(a), "l"(b));
}

// scalar gemv: acc[j] += v[k] * W[k][j], W in shared as float4 rows (64x64)
__device__ __forceinline__ void gemv64(const float* v, const float4* sW, float* acc) {
#pragma unroll
    for (int k = 0; k < 64; k++) {
        float vk = v[k];
#pragma unroll
        for (int j4 = 0; j4 < 16; j4++) {
            float4 w = sW[k * 16 + j4];
            acc[4 * j4 + 0] = fmaf(vk, w.x, acc[4 * j4 + 0]);
            acc[4 * j4 + 1] = fmaf(vk, w.y, acc[4 * j4 + 1]);
            acc[4 * j4 + 2] = fmaf(vk, w.z, acc[4 * j4 + 2]);
            acc[4 * j4 + 3] = fmaf(vk, w.w, acc[4 * j4 + 3]);
        }
    }
}

// ---------------------------------------------------------------------------
__global__ void zero_kernel(int G) {
    int total4 = G * 16;
    for (int i = blockIdx.x * blockDim.x + threadIdx.x; i < total4;
         i += gridDim.x * blockDim.x)
        reinterpret_cast<float4*>(g_sums)[i] = make_float4(0.f, 0.f, 0.f, 0.f);
    for (int i = blockIdx.x * blockDim.x + threadIdx.x; i < G;
         i += gridDim.x * blockDim.x)
        g_cnt[i] = 0.f;
}

// ---------------------------------------------------------------------------
__global__ void fold_kernel(const float* __restrict__ node_w2,
                            const float* __restrict__ node_b2,
                            const float* __restrict__ edge_w2,
                            const float* __restrict__ edge_b2,
                            const float* __restrict__ msg_w1,
                            const float* __restrict__ msg_b1) {
    int j = threadIdx.x & 63;
    int q = threadIdx.x >> 6;  // 0..3
    for (int i = q * 16; i < q * 16 + 16; i++) {
        float a = 0.f, b = 0.f;
        for (int k = 0; k < 64; k++) {
            a = fmaf(node_w2[i * 64 + k], msg_w1[k * 64 + j], a);
            b = fmaf(edge_w2[i * 64 + k], msg_w1[(64 + k) * 64 + j], b);
        }
        g_Wf2[i * 64 + j] = a;
        g_Wf[i * 64 + j]  = b;
    }
    if (q == 0) {
        float c = msg_b1[j];
        for (int k = 0; k < 64; k++) {
            c = fmaf(node_b2[k], msg_w1[k * 64 + j], c);
            c = fmaf(edge_b2[k], msg_w1[(64 + k) * 64 + j], c);
        }
        g_cA[j] = c;
    }
}

// ---------------------------------------------------------------------------
// Per-node precompute: A'[n] = cA + silu(x@node_w1 + node_b1) @ Wf2
//                      C[n]  = edge_b1 + pos[n] @ edge_w1[0:3]
// ---------------------------------------------------------------------------
__global__ __launch_bounds__(128) void node_kernel(
    const float* __restrict__ x, const float* __restrict__ pos,
    const float* __restrict__ node_w1, const float* __restrict__ node_b1,
    const float* __restrict__ edge_w1, const float* __restrict__ edge_b1,
    int N) {
    __shared__ float4 sW1[HD * 16];
    __shared__ float4 sWf2[HD * 16];
    __shared__ float  sEw[3 * 64];
    __shared__ float  sB1[64], sCA[64], sEb[64];

    for (int i = threadIdx.x; i < HD * 16; i += blockDim.x) {
        sW1[i]  = reinterpret_cast<const float4*>(node_w1)[i];
        sWf2[i] = reinterpret_cast<const float4*>(g_Wf2)[i];
    }
    for (int i = threadIdx.x; i < 192; i += blockDim.x) sEw[i] = edge_w1[i];
    if (threadIdx.x < 64) {
        sB1[threadIdx.x] = node_b1[threadIdx.x];
        sCA[threadIdx.x] = g_cA[threadIdx.x];
        sEb[threadIdx.x] = edge_b1[threadIdx.x];
    }
    __syncthreads();

    for (int n = blockIdx.x * blockDim.x + threadIdx.x; n < N;
         n += gridDim.x * blockDim.x) {
        float acc[64];
#pragma unroll
        for (int j = 0; j < 64; j++) acc[j] = sB1[j];

        const float4* xr = reinterpret_cast<const float4*>(x + (size_t)n * 64);
#pragma unroll
        for (int k4 = 0; k4 < 16; k4++) {
            float4 xv = __ldg(xr + k4);
            float xs[4] = {xv.x, xv.y, xv.z, xv.w};
#pragma unroll
            for (int kk = 0; kk < 4; kk++) {
                float vk = xs[kk];
                int k = 4 * k4 + kk;
#pragma unroll
                for (int j4 = 0; j4 < 16; j4++) {
                    float4 w = sW1[k * 16 + j4];
                    acc[4 * j4 + 0] = fmaf(vk, w.x, acc[4 * j4 + 0]);
                    acc[4 * j4 + 1] = fmaf(vk, w.y, acc[4 * j4 + 1]);
                    acc[4 * j4 + 2] = fmaf(vk, w.z, acc[4 * j4 + 2]);
                    acc[4 * j4 + 3] = fmaf(vk, w.w, acc[4 * j4 + 3]);
                }
            }
        }

        float v[64];
#pragma unroll
        for (int j = 0; j < 64; j++) v[j] = silu_f(acc[j]);

        float acc2[64];
#pragma unroll
        for (int j = 0; j < 64; j++) acc2[j] = sCA[j];
        gemv64(v, sWf2, acc2);

        float4* Arow = reinterpret_cast<float4*>(g_A + (size_t)n * 64);
#pragma unroll
        for (int j4 = 0; j4 < 16; j4++)
            Arow[j4] = make_float4(acc2[4 * j4 + 0], acc2[4 * j4 + 1],
                                   acc2[4 * j4 + 2], acc2[4 * j4 + 3]);

        float px = pos[n * 3 + 0], py = pos[n * 3 + 1], pz = pos[n * 3 + 2];
        float4* Crow = reinterpret_cast<float4*>(g_C + (size_t)n * 64);
#pragma unroll
        for (int j4 = 0; j4 < 16; j4++) {
            float c[4];
#pragma unroll
            for (int kk = 0; kk < 4; kk++) {
                int j = 4 * j4 + kk;
                c[kk] = sEb[j];
                c[kk] = fmaf(px, sEw[j], c[kk]);
                c[kk] = fmaf(py, sEw[64 + j], c[kk]);
                c[kk] = fmaf(pz, sEw[128 + j], c[kk]);
            }
            Crow[j4] = make_float4(c[0], c[1], c[2], c[3]);
        }
    }
}

// ---------------------------------------------------------------------------
// Per-edge: t1 = C[s] + trel@edge_w1[3:6]; m1 = A'[s] + silu(t1)@Wf;
//           scatter silu(m1) into g_sums (msg_w2 applied later, per cell).
// Packed f32x2 FMA, 32-wide half-split accumulators, vector red.v4 atomics.
// ---------------------------------------------------------------------------
__global__ __launch_bounds__(128, 4) void edge_kernel(
    const int* __restrict__ src, const int* __restrict__ tgt,
    const float* __restrict__ node_pos, const float* __restrict__ grid_pos,
    const float* __restrict__ orient,
    const float* __restrict__ edge_w1,
    int E, int G) {
    // Wf rows as 16B vectors (2 x u64 per vector)
    __shared__ ulonglong2 sWf[HD * 16];   // [k][j4], 16 KB
    __shared__ float      sEw[3 * 64];

    for (int i = threadIdx.x; i < HD * 16; i += blockDim.x) {
        const float4 w = reinterpret_cast<const float4*>(g_Wf)[i];
        sWf[i].x = pack2(w.x, w.y);
        sWf[i].y = pack2(w.z, w.w);
    }
    for (int i = threadIdx.x; i < 192; i += blockDim.x) sEw[i] = edge_w1[192 + i];
    __syncthreads();

    for (int e = blockIdx.x * blockDim.x + threadIdx.x; e < E;
         e += gridDim.x * blockDim.x) {
        int s = src[e];
        int t = tgt[e];
        if (t < 0 || t >= G) continue;

        float px = node_pos[s * 3 + 0], py = node_pos[s * 3 + 1], pz = node_pos[s * 3 + 2];
        float rx = grid_pos[t * 3 + 0] - px;
        float ry = grid_pos[t * 3 + 1] - py;
        float rz = grid_pos[t * 3 + 2] - pz;
        const float* R = orient + (size_t)s * 9;
        float t0 = rx * R[0] + ry * R[3] + rz * R[6];
        float t1 = rx * R[1] + ry * R[4] + rz * R[7];
        float t2 = rx * R[2] + ry * R[5] + rz * R[8];

        // v = silu(C[s] + trel @ edge_w1[3:6])
        float v[64];
        const float4* Crow = reinterpret_cast<const float4*>(g_C + (size_t)s * 64);
#pragma unroll
        for (int j4 = 0; j4 < 16; j4++) {
            float4 c = __ldg(Crow + j4);
            float cv[4] = {c.x, c.y, c.z, c.w};
#pragma unroll
            for (int kk = 0; kk < 4; kk++) {
                int j = 4 * j4 + kk;
                float a = cv[kk];
                a = fmaf(t0, sEw[j], a);
                a = fmaf(t1, sEw[64 + j], a);
                a = fmaf(t2, sEw[128 + j], a);
                v[j] = silu_f(a);
            }
        }

        const float4* Arow = reinterpret_cast<const float4*>(g_A + (size_t)s * 64);
        float* srow = g_sums + (size_t)t * 64;

#pragma unroll 1
        for (int half = 0; half < 2; half++) {
            unsigned long long acc2[16];
#pragma unroll
            for (int j4 = 0; j4 < 8; j4++) {
                float4 a = __ldg(Arow + half * 8 + j4);
                acc2[2 * j4 + 0] = pack2(a.x, a.y);
                acc2[2 * j4 + 1] = pack2(a.z, a.w);
            }
#pragma unroll
            for (int k = 0; k < 64; k++) {
                unsigned long long vp = bcast2(v[k]);
                const ulonglong2* wr = &sWf[k * 16 + half * 8];
#pragma unroll
                for (int j4 = 0; j4 < 8; j4++) {
                    ulonglong2 w = wr[j4];
                    fma2(acc2[2 * j4 + 0], vp, w.x);
                    fma2(acc2[2 * j4 + 1], vp, w.y);
                }
            }
            // silu + vector atomic scatter
#pragma unroll
            for (int j4 = 0; j4 < 8; j4++) {
                float a0, a1, a2, a3;
                unpack2(acc2[2 * j4 + 0], a0, a1);
                unpack2(acc2[2 * j4 + 1], a2, a3);
                a0 = silu_f(a0); a1 = silu_f(a1);
                a2 = silu_f(a2); a3 = silu_f(a3);
                float* p = srow + half * 32 + j4 * 4;
                asm volatile("red.global.add.v4.f32 [%0], {%1, %2, %3, %4};"
                             :: "l"(p), "f"(a0), "f"(a1), "f"(a2), "f"(a3)
                             : "memory");
            }
        }
        atomicAdd(&g_cnt[t], 1.0f);
    }
}

// ---------------------------------------------------------------------------
// Finalize: mm = (S @ msg_w2) / max(cnt,1) + msg_b2 * (cnt/max(cnt,1));
//           out = silu(mm@upd_w1+b1)@upd_w2+b2
// ---------------------------------------------------------------------------
__global__ __launch_bounds__(128) void final_kernel(
    const float* __restrict__ msg_w2, const float* __restrict__ msg_b2,
    const float* __restrict__ upd_w1, const float* __restrict__ upd_b1,
    const float* __restrict__ upd_w2, const float* __restrict__ upd_b2,
    float* __restrict__ out, int G) {
    __shared__ float4 sM2[HD * 16];
    __shared__ float4 sU1[HD * 16];
    __shared__ float4 sU2[HD * 16];
    __shared__ float  sMB[64], sB1[64], sB2[64];

    for (int i = threadIdx.x; i < HD * 16; i += blockDim.x) {
        sM2[i] = reinterpret_cast<const float4*>(msg_w2)[i];
        sU1[i] = reinterpret_cast<const float4*>(upd_w1)[i];
        sU2[i] = reinterpret_cast<const float4*>(upd_w2)[i];
    }
    if (threadIdx.x < 64) {
        sMB[threadIdx.x] = msg_b2[threadIdx.x];
        sB1[threadIdx.x] = upd_b1[threadIdx.x];
        sB2[threadIdx.x] = upd_b2[threadIdx.x];
    }
    __syncthreads();

    for (int g = blockIdx.x * blockDim.x + threadIdx.x; g < G;
         g += gridDim.x * blockDim.x) {
        float cnt = g_cnt[g];
        float inv = __fdividef(1.0f, fmaxf(cnt, 1.0f));
        float bscale = cnt * inv;  // 1 if cnt>=1, 0 if cnt==0

        float v[64];
        const float4* Srow = reinterpret_cast<const float4*>(g_sums + (size_t)g * 64);
#pragma unroll
        for (int j4 = 0; j4 < 16; j4++) {
            float4 sv = Srow[j4];
            v[4 * j4 + 0] = sv.x; v[4 * j4 + 1] = sv.y;
            v[4 * j4 + 2] = sv.z; v[4 * j4 + 3] = sv.w;
        }

        // mm = (S @ msg_w2) * inv + msg_b2 * bscale
        float acc[64];
#pragma unroll
        for (int j = 0; j < 64; j++) acc[j] = 0.f;
        gemv64(v, sM2, acc);
#pragma unroll
        for (int j = 0; j < 64; j++) v[j] = fmaf(acc[j], inv, sMB[j] * bscale);

        // upd MLP
#pragma unroll
        for (int j = 0; j < 64; j++) acc[j] = sB1[j];
        gemv64(v, sU1, acc);
#pragma unroll
        for (int j = 0; j < 64; j++) v[j] = silu_f(acc[j]);

#pragma unroll
        for (int j = 0; j < 64; j++) acc[j] = sB2[j];
        gemv64(v, sU2, acc);

        float4* orow = reinterpret_cast<float4*>(out + (size_t)g * 64);
#pragma unroll
        for (int j4 = 0; j4 < 16; j4++)
            orow[j4] = make_float4(acc[4 * j4 + 0], acc[4 * j4 + 1],
                                   acc[4 * j4 + 2], acc[4 * j4 + 3]);
    }
}

// ---------------------------------------------------------------------------
extern "C" void kernel_launch(void* const* d_in, const int* in_sizes, int n_in,
                              void* d_out, int out_size) {
    const float* node_features = (const float*)d_in[0];
    const float* node_pos      = (const float*)d_in[1];
    const float* grid_pos      = (const float*)d_in[2];
    const float* orientations  = (const float*)d_in[3];
    const int*   edge_index    = (const int*)d_in[4];
    const float* node_w1 = (const float*)d_in[5];
    const float* node_b1 = (const float*)d_in[6];
    const float* node_w2 = (const float*)d_in[7];
    const float* node_b2 = (const float*)d_in[8];
    const float* edge_w1 = (const float*)d_in[9];
    const float* edge_b1 = (const float*)d_in[10];
    const float* edge_w2 = (const float*)d_in[11];
    const float* edge_b2 = (const float*)d_in[12];
    const float* msg_w1  = (const float*)d_in[13];
    const float* msg_b1  = (const float*)d_in[14];
    const float* msg_w2  = (const float*)d_in[15];
    const float* msg_b2  = (const float*)d_in[16];
    const float* upd_w1  = (const float*)d_in[17];
    const float* upd_b1  = (const float*)d_in[18];
    const float* upd_w2  = (const float*)d_in[19];
    const float* upd_b2  = (const float*)d_in[20];

    int N = in_sizes[0] / 64;
    int G = in_sizes[2] / 3;
    int E = in_sizes[4] / 2;
    const int* src = edge_index;
    const int* tgt = edge_index + E;

    zero_kernel<<<256, 256>>>(G);
    fold_kernel<<<1, 256>>>(node_w2, node_b2, edge_w2, edge_b2, msg_w1, msg_b1);
    node_kernel<<<(N + 127) / 128, 128>>>(node_features, node_pos,
                                          node_w1, node_b1, edge_w1, edge_b1, N);
    int nb = 592;  // 148 SMs x 4 blocks
    if ((long long)nb * 128 > E) nb = (E + 127) / 128;
    edge_kernel<<<nb, 128>>>(src, tgt, node_pos, grid_pos, orientations,
                             edge_w1, E, G);
    final_kernel<<<(G + 127) / 128, 128>>>(msg_w2, msg_b2,
                                           upd_w1, upd_b1, upd_w2, upd_b2,
                                           (float*)d_out, G);
}

// round 8
// speedup vs baseline: 3.4768x; 1.4912x over previous
#include <cuda_runtime.h>

#define HD 64
#define NMAX 100000
#define GMAX 32768

// Scratch (no allocations allowed -> __device__ globals)
__device__ __align__(16) float g_A[NMAX * HD];   // cA + silu(n1) @ Wf2 (pre-silu m1 source part)
__device__ __align__(16) float g_C[NMAX * HD];   // edge_b1 + pos @ edge_w1[0:3]
__device__ __align__(16) float g_Wf[HD * HD];    // edge_w2 @ msg_w1[64:128]
__device__ __align__(16) float g_Wf2[HD * HD];   // node_w2 @ msg_w1[0:64]
__device__ __align__(16) float g_WfU[HD * HD];   // msg_w2 @ upd_w1
__device__ __align__(16) float g_cA[HD];         // msg_b1 + node_b2@msg_w1_top + edge_b2@msg_w1_bot
__device__ __align__(16) float g_cB[HD];         // msg_b2 @ upd_w1
__device__ __align__(16) float g_sums[GMAX * HD];
__device__ float g_cnt[GMAX];

__device__ __forceinline__ float silu_f(float x) {
    return __fdividef(x, 1.0f + __expf(-x));
}
__device__ __forceinline__ unsigned long long pack2(float x, float y) {
    unsigned long long r;
    asm("mov.b64 %0, {%1, %2};" : "=l"(r) : "f"(x), "f"(y));
    return r;
}
__device__ __forceinline__ void unpack2(unsigned long long v, float& x, float& y) {
    asm("mov.b64 {%0, %1}, %2;" : "=f"(x), "=f"(y) : "l"(v));
}
__device__ __forceinline__ unsigned long long bcast2(float x) {
    unsigned long long r;
    asm("mov.b64 %0, {%1, %1};" : "=l"(r) : "f"(x));
    return r;
}
__device__ __forceinline__ void fma2(unsigned long long& acc, unsigned long long a,
                                     unsigned long long b) {
    asm("fma.rn.f32x2 %0, %1, %2, %0;" : "+l"(acc) : "l"(a), "l"(b));
}

// ---------------------------------------------------------------------------
__global__ void zero_kernel(int G) {
    int total4 = G * 16;
    for (int i = blockIdx.x * blockDim.x + threadIdx.x; i < total4;
         i += gridDim.x * blockDim.x)
        reinterpret_cast<float4*>(g_sums)[i] = make_float4(0.f, 0.f, 0.f, 0.f);
    for (int i = blockIdx.x * blockDim.x + threadIdx.x; i < G;
         i += gridDim.x * blockDim.x)
        g_cnt[i] = 0.f;
}

// ---------------------------------------------------------------------------
// Parallel weight folds: one block per output row, 3 thread-groups of 64.
// ---------------------------------------------------------------------------
__global__ void fold_kernel(const float* __restrict__ node_w2,
                            const float* __restrict__ edge_w2,
                            const float* __restrict__ msg_w1,
                            const float* __restrict__ msg_w2,
                            const float* __restrict__ upd_w1) {
    int i = blockIdx.x;
    int j = threadIdx.x & 63;
    int which = threadIdx.x >> 6;
    float a = 0.f;
    if (which == 0) {
        for (int k = 0; k < 64; k++)
            a = fmaf(__ldg(node_w2 + i * 64 + k), __ldg(msg_w1 + k * 64 + j), a);
        g_Wf2[i * 64 + j] = a;
    } else if (which == 1) {
        for (int k = 0; k < 64; k++)
            a = fmaf(__ldg(edge_w2 + i * 64 + k), __ldg(msg_w1 + (64 + k) * 64 + j), a);
        g_Wf[i * 64 + j] = a;
    } else {
        for (int k = 0; k < 64; k++)
            a = fmaf(__ldg(msg_w2 + i * 64 + k), __ldg(upd_w1 + k * 64 + j), a);
        g_WfU[i * 64 + j] = a;
    }
}

__global__ void bias_kernel(const float* __restrict__ node_b2,
                            const float* __restrict__ edge_b2,
                            const float* __restrict__ msg_w1,
                            const float* __restrict__ msg_b1,
                            const float* __restrict__ msg_b2,
                            const float* __restrict__ upd_w1) {
    int j = threadIdx.x & 63;
    if (threadIdx.x < 64) {
        float c = msg_b1[j];
        for (int k = 0; k < 64; k++) {
            c = fmaf(node_b2[k], msg_w1[k * 64 + j], c);
            c = fmaf(edge_b2[k], msg_w1[(64 + k) * 64 + j], c);
        }
        g_cA[j] = c;
    } else {
        float c = 0.f;
        for (int k = 0; k < 64; k++)
            c = fmaf(msg_b2[k], upd_w1[k * 64 + j], c);
        g_cB[j] = c;
    }
}

// ---------------------------------------------------------------------------
// Per-node precompute: A'[n] = cA + silu(x@node_w1 + node_b1) @ Wf2
//                      C[n]  = edge_b1 + pos[n] @ edge_w1[0:3]
// f32x2 packed, half-split accumulators to bound registers.
// ---------------------------------------------------------------------------
__global__ __launch_bounds__(128, 4) void node_kernel(
    const float* __restrict__ x, const float* __restrict__ pos,
    const float* __restrict__ node_w1, const float* __restrict__ node_b1,
    const float* __restrict__ edge_w1, const float* __restrict__ edge_b1,
    int N) {
    __shared__ ulonglong2 sW1[HD * 16];    // node_w1 rows as f32 pairs
    __shared__ ulonglong2 sWf2[HD * 16];
    __shared__ float sEw[3 * 64];
    __shared__ float sB1[64], sCA[64], sEb[64];

    for (int i = threadIdx.x; i < HD * 16; i += blockDim.x) {
        sW1[i]  = reinterpret_cast<const ulonglong2*>(node_w1)[i];
        sWf2[i] = reinterpret_cast<const ulonglong2*>(g_Wf2)[i];
    }
    for (int i = threadIdx.x; i < 192; i += blockDim.x) sEw[i] = edge_w1[i];
    if (threadIdx.x < 64) {
        sB1[threadIdx.x] = node_b1[threadIdx.x];
        sCA[threadIdx.x] = g_cA[threadIdx.x];
        sEb[threadIdx.x] = edge_b1[threadIdx.x];
    }
    __syncthreads();

    for (int n = blockIdx.x * blockDim.x + threadIdx.x; n < N;
         n += gridDim.x * blockDim.x) {
        const float4* xr = reinterpret_cast<const float4*>(x + (size_t)n * 64);
        float v[64];
        // GEMV1 (x @ node_w1 + b1), outputs in halves of 32
#pragma unroll 1
        for (int h = 0; h < 2; h++) {
            unsigned long long acc[16];
#pragma unroll
            for (int p = 0; p < 16; p++)
                acc[p] = pack2(sB1[h * 32 + 2 * p], sB1[h * 32 + 2 * p + 1]);
#pragma unroll 2
            for (int k4 = 0; k4 < 16; k4++) {
                float4 xv = __ldg(xr + k4);
                float xs[4] = {xv.x, xv.y, xv.z, xv.w};
#pragma unroll
                for (int kk = 0; kk < 4; kk++) {
                    int k = 4 * k4 + kk;
                    unsigned long long vp = bcast2(xs[kk]);
                    const ulonglong2* wr = sW1 + k * 16 + h * 8;
#pragma unroll
                    for (int q = 0; q < 8; q++) {
                        ulonglong2 w = wr[q];
                        fma2(acc[2 * q], vp, w.x);
                        fma2(acc[2 * q + 1], vp, w.y);
                    }
                }
            }
#pragma unroll
            for (int p = 0; p < 16; p++) {
                float a, b;
                unpack2(acc[p], a, b);
                v[h * 32 + 2 * p] = silu_f(a);
                v[h * 32 + 2 * p + 1] = silu_f(b);
            }
        }
        // GEMV2 (v @ Wf2 + cA) -> g_A
        float4* Arow = reinterpret_cast<float4*>(g_A + (size_t)n * 64);
#pragma unroll 1
        for (int h = 0; h < 2; h++) {
            unsigned long long acc[16];
#pragma unroll
            for (int p = 0; p < 16; p++)
                acc[p] = pack2(sCA[h * 32 + 2 * p], sCA[h * 32 + 2 * p + 1]);
#pragma unroll 4
            for (int k = 0; k < 64; k++) {
                unsigned long long vp = bcast2(v[k]);
                const ulonglong2* wr = sWf2 + k * 16 + h * 8;
#pragma unroll
                for (int q = 0; q < 8; q++) {
                    ulonglong2 w = wr[q];
                    fma2(acc[2 * q], vp, w.x);
                    fma2(acc[2 * q + 1], vp, w.y);
                }
            }
#pragma unroll
            for (int p = 0; p < 8; p++) {
                float a0, a1, a2, a3;
                unpack2(acc[2 * p], a0, a1);
                unpack2(acc[2 * p + 1], a2, a3);
                Arow[h * 8 + p] = make_float4(a0, a1, a2, a3);
            }
        }
        // C row
        float px = pos[n * 3 + 0], py = pos[n * 3 + 1], pz = pos[n * 3 + 2];
        float4* Crow = reinterpret_cast<float4*>(g_C + (size_t)n * 64);
#pragma unroll
        for (int j4 = 0; j4 < 16; j4++) {
            float c[4];
#pragma unroll
            for (int kk = 0; kk < 4; kk++) {
                int j = 4 * j4 + kk;
                c[kk] = sEb[j];
                c[kk] = fmaf(px, sEw[j], c[kk]);
                c[kk] = fmaf(py, sEw[64 + j], c[kk]);
                c[kk] = fmaf(pz, sEw[128 + j], c[kk]);
            }
            Crow[j4] = make_float4(c[0], c[1], c[2], c[3]);
        }
    }
}

// ---------------------------------------------------------------------------
// Edge kernel, tile-GEMM version. Per 128-edge tile:
//   Phase A: thread e computes v = silu(C[s] + trel@edge_w1[3:6]) -> smem vT
//   Phase B: 128x64x64 register-tiled GEMM (8x8/thread, f32x2)
//   Phase C: + A'[s], silu, red.v4 scatter to g_sums
// Dynamic smem: vT4 (32KB) + sWf (16KB) + sEw + sidx/tidx = 50944 B.
// ---------------------------------------------------------------------------
#define EDGE_TILE 128
#define EDGE_SMEM (32768 + 16384 + 768 + 512 + 512)

__global__ __launch_bounds__(128, 4) void edge_kernel(
    const int* __restrict__ src, const int* __restrict__ tgt,
    const float* __restrict__ node_pos, const float* __restrict__ grid_pos,
    const float* __restrict__ orient,
    const float* __restrict__ edge_w1,
    int E, int G) {
    extern __shared__ char smem[];
    float4* vT4 = reinterpret_cast<float4*>(smem);                       // [64][32] float4 = [64][128] f
    float* vTf = reinterpret_cast<float*>(smem);
    ulonglong2* sWf = reinterpret_cast<ulonglong2*>(smem + 32768);       // [64][16]
    float* sEw = reinterpret_cast<float*>(smem + 32768 + 16384);         // 192 floats
    int* s_sidx = reinterpret_cast<int*>(smem + 32768 + 16384 + 768);    // 128
    int* s_tidx = s_sidx + 128;                                          // 128

    const int tid = threadIdx.x;
    for (int i = tid; i < HD * 16; i += blockDim.x)
        sWf[i] = reinterpret_cast<const ulonglong2*>(g_Wf)[i];
    for (int i = tid; i < 192; i += blockDim.x) sEw[i] = edge_w1[192 + i];
    __syncthreads();

    const int m0 = (tid >> 3) << 3;   // 16 m-tiles
    const int n0 = (tid & 7) << 3;    // 8 n-tiles

    int numTiles = (E + EDGE_TILE - 1) / EDGE_TILE;
    for (int tile = blockIdx.x; tile < numTiles; tile += gridDim.x) {
        int base = tile * EDGE_TILE;
        int e = base + tid;

        // ---- Phase A ----
        int s = 0, t = -1;
        if (e < E) {
            s = src[e];
            int tt = tgt[e];
            if (tt >= 0 && tt < G) t = tt;
        }
        float t0 = 0.f, t1 = 0.f, t2 = 0.f;
        bool val = (t >= 0);
        if (val) {
            float px = node_pos[s * 3 + 0], py = node_pos[s * 3 + 1],
                  pz = node_pos[s * 3 + 2];
            float rx = grid_pos[t * 3 + 0] - px;
            float ry = grid_pos[t * 3 + 1] - py;
            float rz = grid_pos[t * 3 + 2] - pz;
            const float* R = orient + (size_t)s * 9;
            t0 = rx * R[0] + ry * R[3] + rz * R[6];
            t1 = rx * R[1] + ry * R[4] + rz * R[7];
            t2 = rx * R[2] + ry * R[5] + rz * R[8];
        }
        {
            const float4* Crow = reinterpret_cast<const float4*>(g_C + (size_t)s * 64);
            float* col = vTf + tid;
#pragma unroll
            for (int j4 = 0; j4 < 16; j4++) {
                float4 c = __ldg(Crow + j4);
                float cv[4] = {c.x, c.y, c.z, c.w};
#pragma unroll
                for (int kk = 0; kk < 4; kk++) {
                    int j = 4 * j4 + kk;
                    float a = cv[kk];
                    a = fmaf(t0, sEw[j], a);
                    a = fmaf(t1, sEw[64 + j], a);
                    a = fmaf(t2, sEw[128 + j], a);
                    col[j * 128] = val ? silu_f(a) : 0.f;
                }
            }
        }
        s_sidx[tid] = s;
        s_tidx[tid] = t;
        if (val) atomicAdd(&g_cnt[t], 1.0f);
        __syncthreads();

        // ---- Phase B: GEMM ----
        unsigned long long acc[32];
#pragma unroll
        for (int i = 0; i < 32; i++) acc[i] = 0ULL;
#pragma unroll 4
        for (int k = 0; k < 64; k++) {
            float4 a0 = vT4[k * 32 + (m0 >> 2)];
            float4 a1 = vT4[k * 32 + (m0 >> 2) + 1];
            ulonglong2 w0 = sWf[k * 16 + (n0 >> 2)];
            ulonglong2 w1 = sWf[k * 16 + (n0 >> 2) + 1];
            float av[8] = {a0.x, a0.y, a0.z, a0.w, a1.x, a1.y, a1.z, a1.w};
#pragma unroll
            for (int mi = 0; mi < 8; mi++) {
                unsigned long long ap = bcast2(av[mi]);
                fma2(acc[mi * 4 + 0], ap, w0.x);
                fma2(acc[mi * 4 + 1], ap, w0.y);
                fma2(acc[mi * 4 + 2], ap, w1.x);
                fma2(acc[mi * 4 + 3], ap, w1.y);
            }
        }

        // ---- Phase C: bias + silu + scatter ----
#pragma unroll
        for (int mi = 0; mi < 8; mi++) {
            int m = m0 + mi;
            int tt = s_tidx[m];
            if (tt < 0) continue;
            int ss = s_sidx[m];
            const float4* Ar =
                reinterpret_cast<const float4*>(g_A + (size_t)ss * 64 + n0);
            float4 b0 = __ldg(Ar), b1 = __ldg(Ar + 1);
            float a0, a1, a2, a3, a4, a5, a6, a7;
            unpack2(acc[mi * 4 + 0], a0, a1);
            unpack2(acc[mi * 4 + 1], a2, a3);
            unpack2(acc[mi * 4 + 2], a4, a5);
            unpack2(acc[mi * 4 + 3], a6, a7);
            a0 = silu_f(a0 + b0.x); a1 = silu_f(a1 + b0.y);
            a2 = silu_f(a2 + b0.z); a3 = silu_f(a3 + b0.w);
            a4 = silu_f(a4 + b1.x); a5 = silu_f(a5 + b1.y);
            a6 = silu_f(a6 + b1.z); a7 = silu_f(a7 + b1.w);
            float* p = g_sums + (size_t)tt * 64 + n0;
            asm volatile("red.global.add.v4.f32 [%0], {%1, %2, %3, %4};"
                         :: "l"(p), "f"(a0), "f"(a1), "f"(a2), "f"(a3) : "memory");
            asm volatile("red.global.add.v4.f32 [%0], {%1, %2, %3, %4};"
                         :: "l"(p + 4), "f"(a4), "f"(a5), "f"(a6), "f"(a7) : "memory");
        }
        __syncthreads();
    }
}

// ---------------------------------------------------------------------------
// Finalize: z = (S @ WfU)*inv + cB*bscale + upd_b1; out = silu(z)@upd_w2 + b2
// (msg_w2@upd_w1 folded offline; S row re-read per half to bound registers)
// ---------------------------------------------------------------------------
__global__ __launch_bounds__(128, 4) void final_kernel(
    const float* __restrict__ upd_b1,
    const float* __restrict__ upd_w2, const float* __restrict__ upd_b2,
    float* __restrict__ out, int G) {
    __shared__ ulonglong2 sWU[HD * 16];
    __shared__ ulonglong2 sU2[HD * 16];
    __shared__ float sCB[64], sB1[64], sB2[64];

    for (int i = threadIdx.x; i < HD * 16; i += blockDim.x) {
        sWU[i] = reinterpret_cast<const ulonglong2*>(g_WfU)[i];
        sU2[i] = reinterpret_cast<const ulonglong2*>(upd_w2)[i];
    }
    if (threadIdx.x < 64) {
        sCB[threadIdx.x] = g_cB[threadIdx.x];
        sB1[threadIdx.x] = upd_b1[threadIdx.x];
        sB2[threadIdx.x] = upd_b2[threadIdx.x];
    }
    __syncthreads();

    for (int g = blockIdx.x * blockDim.x + threadIdx.x; g < G;
         g += gridDim.x * blockDim.x) {
        float cnt = g_cnt[g];
        float inv = __fdividef(1.0f, fmaxf(cnt, 1.0f));
        float bscale = cnt * inv;
        const float4* Srow = reinterpret_cast<const float4*>(g_sums + (size_t)g * 64);

        float vz[64];
#pragma unroll 1
        for (int h = 0; h < 2; h++) {
            unsigned long long acc[16];
#pragma unroll
            for (int p = 0; p < 16; p++) acc[p] = 0ULL;
#pragma unroll 2
            for (int k4 = 0; k4 < 16; k4++) {
                float4 sv = Srow[k4];
                float xs[4] = {sv.x, sv.y, sv.z, sv.w};
#pragma unroll
                for (int kk = 0; kk < 4; kk++) {
                    int k = 4 * k4 + kk;
                    unsigned long long vp = bcast2(xs[kk]);
                    const ulonglong2* wr = sWU + k * 16 + h * 8;
#pragma unroll
                    for (int q = 0; q < 8; q++) {
                        ulonglong2 w = wr[q];
                        fma2(acc[2 * q], vp, w.x);
                        fma2(acc[2 * q + 1], vp, w.y);
                    }
                }
            }
#pragma unroll
            for (int p = 0; p < 16; p++) {
                float a, b;
                unpack2(acc[p], a, b);
                int j = h * 32 + 2 * p;
                vz[j] = silu_f(fmaf(a, inv, fmaf(sCB[j], bscale, sB1[j])));
                vz[j + 1] =
                    silu_f(fmaf(b, inv, fmaf(sCB[j + 1], bscale, sB1[j + 1])));
            }
        }

        float4* orow = reinterpret_cast<float4*>(out + (size_t)g * 64);
#pragma unroll 1
        for (int h = 0; h < 2; h++) {
            unsigned long long acc[16];
#pragma unroll
            for (int p = 0; p < 16; p++)
                acc[p] = pack2(sB2[h * 32 + 2 * p], sB2[h * 32 + 2 * p + 1]);
#pragma unroll 4
            for (int k = 0; k < 64; k++) {
                unsigned long long vp = bcast2(vz[k]);
                const ulonglong2* wr = sU2 + k * 16 + h * 8;
#pragma unroll
                for (int q = 0; q < 8; q++) {
                    ulonglong2 w = wr[q];
                    fma2(acc[2 * q], vp, w.x);
                    fma2(acc[2 * q + 1], vp, w.y);
                }
            }
#pragma unroll
            for (int p = 0; p < 8; p++) {
                float a0, a1, a2, a3;
                unpack2(acc[2 * p], a0, a1);
                unpack2(acc[2 * p + 1], a2, a3);
                orow[h * 8 + p] = make_float4(a0, a1, a2, a3);
            }
        }
    }
}

// ---------------------------------------------------------------------------
extern "C" void kernel_launch(void* const* d_in, const int* in_sizes, int n_in,
                              void* d_out, int out_size) {
    const float* node_features = (const float*)d_in[0];
    const float* node_pos      = (const float*)d_in[1];
    const float* grid_pos      = (const float*)d_in[2];
    const float* orientations  = (const float*)d_in[3];
    const int*   edge_index    = (const int*)d_in[4];
    const float* node_w1 = (const float*)d_in[5];
    const float* node_b1 = (const float*)d_in[6];
    const float* node_w2 = (const float*)d_in[7];
    const float* node_b2 = (const float*)d_in[8];
    const float* edge_w1 = (const float*)d_in[9];
    const float* edge_b1 = (const float*)d_in[10];
    const float* edge_w2 = (const float*)d_in[11];
    const float* edge_b2 = (const float*)d_in[12];
    const float* msg_w1  = (const float*)d_in[13];
    const float* msg_b1  = (const float*)d_in[14];
    const float* msg_w2  = (const float*)d_in[15];
    const float* msg_b2  = (const float*)d_in[16];
    const float* upd_w1  = (const float*)d_in[17];
    const float* upd_b1  = (const float*)d_in[18];
    const float* upd_w2  = (const float*)d_in[19];
    const float* upd_b2  = (const float*)d_in[20];

    int N = in_sizes[0] / 64;
    int G = in_sizes[2] / 3;
    int E = in_sizes[4] / 2;
    const int* src = edge_index;
    const int* tgt = edge_index + E;

    cudaFuncSetAttribute(edge_kernel, cudaFuncAttributeMaxDynamicSharedMemorySize,
                         EDGE_SMEM);

    zero_kernel<<<256, 256>>>(G);
    fold_kernel<<<64, 192>>>(node_w2, edge_w2, msg_w1, msg_w2, upd_w1);
    bias_kernel<<<1, 128>>>(node_b2, edge_b2, msg_w1, msg_b1, msg_b2, upd_w1);
    node_kernel<<<(N + 127) / 128, 128>>>(node_features, node_pos,
                                          node_w1, node_b1, edge_w1, edge_b1, N);
    int numTiles = (E + EDGE_TILE - 1) / EDGE_TILE;
    int nb = numTiles < 592 ? numTiles : 592;
    edge_kernel<<<nb, 128, EDGE_SMEM>>>(src, tgt, node_pos, grid_pos,
                                        orientations, edge_w1, E, G);
    final_kernel<<<(G + 127) / 128, 128>>>(upd_b1, upd_w2, upd_b2,
                                           (float*)d_out, G);
}

// round 10
// speedup vs baseline: 3.8596x; 1.1101x over previous
#include <cuda_runtime.h>

#define HD 64
#define NMAX 100000
#define GMAX 32768

// Scratch (no allocations allowed -> __device__ globals)
__device__ __align__(16) float g_A[NMAX * HD];   // cA + silu(n1) @ Wf2
__device__ __align__(16) float g_Wf[HD * HD];    // edge_w2 @ msg_w1[64:128]
__device__ __align__(16) float g_Wf2[HD * HD];   // node_w2 @ msg_w1[0:64]
__device__ __align__(16) float g_WfU[HD * HD];   // msg_w2 @ upd_w1
__device__ __align__(16) float g_cA[HD];
__device__ __align__(16) float g_cB[HD];         // msg_b2 @ upd_w1
__device__ __align__(16) float g_sums[GMAX * HD];
__device__ float g_cnt[GMAX];

// Uniform-address weights -> constant memory (LDCU path, off the L1tex port)
__constant__ __align__(16) float c_W1[HD * HD];   // node_w1
__constant__ __align__(16) float c_WfU[HD * HD];  // msg_w2 @ upd_w1
__constant__ __align__(16) float c_ew[6 * HD];    // edge_w1 (full 6x64)
__constant__ __align__(16) float c_eb1[HD];       // edge_b1
__constant__ __align__(16) float c_nb1[HD];       // node_b1
__constant__ __align__(16) float c_cA[HD];
__constant__ __align__(16) float c_cB[HD];
__constant__ __align__(16) float c_ub1[HD];
__constant__ __align__(16) float c_ub2[HD];

__device__ __forceinline__ float silu_f(float x) {        // exact-ish
    return __fdividef(x, 1.0f + __expf(-x));
}
__device__ __forceinline__ float silu_t(float x) {        // tanh.approx (1 MUFU)
    float h = 0.5f * x, t;
    asm("tanh.approx.f32 %0, %1;" : "=f"(t) : "f"(h));
    return fmaf(h, t, h);
}
__device__ __forceinline__ unsigned long long pack2(float x, float y) {
    unsigned long long r;
    asm("mov.b64 %0, {%1, %2};" : "=l"(r) : "f"(x), "f"(y));
    return r;
}
__device__ __forceinline__ void unpack2(unsigned long long v, float& x, float& y) {
    asm("mov.b64 {%0, %1}, %2;" : "=f"(x), "=f"(y) : "l"(v));
}
__device__ __forceinline__ unsigned long long bcast2(float x) {
    unsigned long long r;
    asm("mov.b64 %0, {%1, %1};" : "=l"(r) : "f"(x));
    return r;
}
__device__ __forceinline__ void fma2(unsigned long long& acc, unsigned long long a,
                                     unsigned long long b) {
    asm("fma.rn.f32x2 %0, %1, %2, %0;" : "+l"(acc) : "l"(a), "l"(b));
}
__device__ __forceinline__ unsigned long long ldc64(const float* p) {
    return *reinterpret_cast<const unsigned long long*>(p);
}
__device__ __forceinline__ ulonglong2 ldc128(const float* p) {
    return *reinterpret_cast<const ulonglong2*>(p);
}

// ---------------------------------------------------------------------------
// Weight folds (device-side; results copied to __constant__ where uniform)
// ---------------------------------------------------------------------------
__global__ void fold_kernel(const float* __restrict__ node_w2,
                            const float* __restrict__ edge_w2,
                            const float* __restrict__ msg_w1,
                            const float* __restrict__ msg_w2,
                            const float* __restrict__ upd_w1) {
    int i = blockIdx.x;
    int j = threadIdx.x & 63;
    int which = threadIdx.x >> 6;
    float a = 0.f;
    if (which == 0) {
        for (int k = 0; k < 64; k++)
            a = fmaf(__ldg(node_w2 + i * 64 + k), __ldg(msg_w1 + k * 64 + j), a);
        g_Wf2[i * 64 + j] = a;
    } else if (which == 1) {
        for (int k = 0; k < 64; k++)
            a = fmaf(__ldg(edge_w2 + i * 64 + k), __ldg(msg_w1 + (64 + k) * 64 + j), a);
        g_Wf[i * 64 + j] = a;
    } else {
        for (int k = 0; k < 64; k++)
            a = fmaf(__ldg(msg_w2 + i * 64 + k), __ldg(upd_w1 + k * 64 + j), a);
        g_WfU[i * 64 + j] = a;
    }
}

__global__ void bias_kernel(const float* __restrict__ node_b2,
                            const float* __restrict__ edge_b2,
                            const float* __restrict__ msg_w1,
                            const float* __restrict__ msg_b1,
                            const float* __restrict__ msg_b2,
                            const float* __restrict__ upd_w1) {
    int j = threadIdx.x & 63;
    if (threadIdx.x < 64) {
        float c = msg_b1[j];
        for (int k = 0; k < 64; k++) {
            c = fmaf(node_b2[k], msg_w1[k * 64 + j], c);
            c = fmaf(edge_b2[k], msg_w1[(64 + k) * 64 + j], c);
        }
        g_cA[j] = c;
    } else {
        float c = 0.f;
        for (int k = 0; k < 64; k++)
            c = fmaf(msg_b2[k], upd_w1[k * 64 + j], c);
        g_cB[j] = c;
    }
}

// ---------------------------------------------------------------------------
// Per-node: A'[n] = cA + silu(x @ c_W1 + nb1) @ Wf2
// GEMV1 reads constant (LDCU), GEMV2 reads shared (LDS) -> two ports.
// ---------------------------------------------------------------------------
__global__ __launch_bounds__(128, 4) void node_kernel(
    const float* __restrict__ x, int N) {
    __shared__ ulonglong2 sWf2[HD * 16];
    for (int i = threadIdx.x; i < HD * 16; i += blockDim.x)
        sWf2[i] = reinterpret_cast<const ulonglong2*>(g_Wf2)[i];
    __syncthreads();

    for (int n = blockIdx.x * blockDim.x + threadIdx.x; n < N;
         n += gridDim.x * blockDim.x) {
        const float4* xr = reinterpret_cast<const float4*>(x + (size_t)n * 64);
        float v[64];
        // GEMV1 from constant memory
#pragma unroll 1
        for (int h = 0; h < 2; h++) {
            unsigned long long acc[16];
#pragma unroll
            for (int p = 0; p < 16; p++) acc[p] = ldc64(c_nb1 + h * 32 + 2 * p);
#pragma unroll 2
            for (int k4 = 0; k4 < 16; k4++) {
                float4 xv = __ldg(xr + k4);
                float xs[4] = {xv.x, xv.y, xv.z, xv.w};
#pragma unroll
                for (int kk = 0; kk < 4; kk++) {
                    int k = 4 * k4 + kk;
                    unsigned long long vp = bcast2(xs[kk]);
#pragma unroll
                    for (int q = 0; q < 8; q++) {
                        ulonglong2 w = ldc128(c_W1 + k * 64 + h * 32 + 4 * q);
                        fma2(acc[2 * q], vp, w.x);
                        fma2(acc[2 * q + 1], vp, w.y);
                    }
                }
            }
#pragma unroll
            for (int p = 0; p < 16; p++) {
                float a, b;
                unpack2(acc[p], a, b);
                v[h * 32 + 2 * p] = silu_f(a);
                v[h * 32 + 2 * p + 1] = silu_f(b);
            }
        }
        // GEMV2 from shared
        float4* Arow = reinterpret_cast<float4*>(g_A + (size_t)n * 64);
#pragma unroll 1
        for (int h = 0; h < 2; h++) {
            unsigned long long acc[16];
#pragma unroll
            for (int p = 0; p < 16; p++) acc[p] = ldc64(c_cA + h * 32 + 2 * p);
#pragma unroll 4
            for (int k = 0; k < 64; k++) {
                unsigned long long vp = bcast2(v[k]);
                const ulonglong2* wr = sWf2 + k * 16 + h * 8;
#pragma unroll
                for (int q = 0; q < 8; q++) {
                    ulonglong2 w = wr[q];
                    fma2(acc[2 * q], vp, w.x);
                    fma2(acc[2 * q + 1], vp, w.y);
                }
            }
#pragma unroll
            for (int p = 0; p < 8; p++) {
                float a0, a1, a2, a3;
                unpack2(acc[2 * p], a0, a1);
                unpack2(acc[2 * p + 1], a2, a3);
                Arow[h * 8 + p] = make_float4(a0, a1, a2, a3);
            }
        }
    }
}

// ---------------------------------------------------------------------------
// Edge kernel (tile-GEMM). Phase A recomputes the edge-layer-1 input inline
// from constant memory (no g_C gather). silu via tanh.approx.
// ---------------------------------------------------------------------------
#define EDGE_TILE 128
#define EDGE_SMEM (32768 + 16384 + 512 + 512)

__global__ __launch_bounds__(128, 4) void edge_kernel(
    const int* __restrict__ src, const int* __restrict__ tgt,
    const float* __restrict__ node_pos, const float* __restrict__ grid_pos,
    const float* __restrict__ orient,
    int E, int G) {
    extern __shared__ char smem[];
    float4* vT4 = reinterpret_cast<float4*>(smem);                  // [64][128] floats
    float* vTf = reinterpret_cast<float*>(smem);
    ulonglong2* sWf = reinterpret_cast<ulonglong2*>(smem + 32768);  // [64][16]
    int* s_sidx = reinterpret_cast<int*>(smem + 32768 + 16384);     // 128
    int* s_tidx = s_sidx + 128;                                     // 128

    const int tid = threadIdx.x;
    for (int i = tid; i < HD * 16; i += blockDim.x)
        sWf[i] = reinterpret_cast<const ulonglong2*>(g_Wf)[i];
    __syncthreads();

    const int m0 = (tid >> 3) << 3;
    const int n0 = (tid & 7) << 3;

    int numTiles = (E + EDGE_TILE - 1) / EDGE_TILE;
    for (int tile = blockIdx.x; tile < numTiles; tile += gridDim.x) {
        int e = tile * EDGE_TILE + tid;

        // ---- Phase A: v = silu(eb1 + [pos,trel] @ edge_w1) ----
        int s = 0, t = -1;
        if (e < E) {
            s = src[e];
            int tt = tgt[e];
            if (tt >= 0 && tt < G) t = tt;
        }
        bool val = (t >= 0);
        float px = node_pos[s * 3 + 0], py = node_pos[s * 3 + 1],
              pz = node_pos[s * 3 + 2];
        float t0 = 0.f, t1 = 0.f, t2 = 0.f;
        if (val) {
            float rx = grid_pos[t * 3 + 0] - px;
            float ry = grid_pos[t * 3 + 1] - py;
            float rz = grid_pos[t * 3 + 2] - pz;
            const float* R = orient + (size_t)s * 9;
            t0 = rx * R[0] + ry * R[3] + rz * R[6];
            t1 = rx * R[1] + ry * R[4] + rz * R[7];
            t2 = rx * R[2] + ry * R[5] + rz * R[8];
        }
        {
            unsigned long long bp0 = bcast2(px), bp1 = bcast2(py), bp2 = bcast2(pz);
            unsigned long long bt0 = bcast2(t0), bt1 = bcast2(t1), bt2 = bcast2(t2);
            float* col = vTf + tid;
#pragma unroll
            for (int p = 0; p < 32; p++) {
                unsigned long long a = ldc64(c_eb1 + 2 * p);
                fma2(a, bp0, ldc64(c_ew + 0 * 64 + 2 * p));
                fma2(a, bp1, ldc64(c_ew + 1 * 64 + 2 * p));
                fma2(a, bp2, ldc64(c_ew + 2 * 64 + 2 * p));
                fma2(a, bt0, ldc64(c_ew + 3 * 64 + 2 * p));
                fma2(a, bt1, ldc64(c_ew + 4 * 64 + 2 * p));
                fma2(a, bt2, ldc64(c_ew + 5 * 64 + 2 * p));
                float x0, x1;
                unpack2(a, x0, x1);
                col[(2 * p) * 128] = val ? silu_t(x0) : 0.f;
                col[(2 * p + 1) * 128] = val ? silu_t(x1) : 0.f;
            }
        }
        s_sidx[tid] = s;
        s_tidx[tid] = t;
        if (val) atomicAdd(&g_cnt[t], 1.0f);
        __syncthreads();

        // ---- Phase B: 128x64x64 GEMM ----
        unsigned long long acc[32];
#pragma unroll
        for (int i = 0; i < 32; i++) acc[i] = 0ULL;
#pragma unroll 4
        for (int k = 0; k < 64; k++) {
            float4 a0 = vT4[k * 32 + (m0 >> 2)];
            float4 a1 = vT4[k * 32 + (m0 >> 2) + 1];
            ulonglong2 w0 = sWf[k * 16 + (n0 >> 2)];
            ulonglong2 w1 = sWf[k * 16 + (n0 >> 2) + 1];
            float av[8] = {a0.x, a0.y, a0.z, a0.w, a1.x, a1.y, a1.z, a1.w};
#pragma unroll
            for (int mi = 0; mi < 8; mi++) {
                unsigned long long ap = bcast2(av[mi]);
                fma2(acc[mi * 4 + 0], ap, w0.x);
                fma2(acc[mi * 4 + 1], ap, w0.y);
                fma2(acc[mi * 4 + 2], ap, w1.x);
                fma2(acc[mi * 4 + 3], ap, w1.y);
            }
        }

        // ---- Phase C: + A'[s], silu, scatter ----
#pragma unroll
        for (int mi = 0; mi < 8; mi++) {
            int m = m0 + mi;
            int tt = s_tidx[m];
            if (tt < 0) continue;
            int ss = s_sidx[m];
            const float4* Ar =
                reinterpret_cast<const float4*>(g_A + (size_t)ss * 64 + n0);
            float4 b0 = __ldg(Ar), b1 = __ldg(Ar + 1);
            float a0, a1, a2, a3, a4, a5, a6, a7;
            unpack2(acc[mi * 4 + 0], a0, a1);
            unpack2(acc[mi * 4 + 1], a2, a3);
            unpack2(acc[mi * 4 + 2], a4, a5);
            unpack2(acc[mi * 4 + 3], a6, a7);
            a0 = silu_t(a0 + b0.x); a1 = silu_t(a1 + b0.y);
            a2 = silu_t(a2 + b0.z); a3 = silu_t(a3 + b0.w);
            a4 = silu_t(a4 + b1.x); a5 = silu_t(a5 + b1.y);
            a6 = silu_t(a6 + b1.z); a7 = silu_t(a7 + b1.w);
            float* p = g_sums + (size_t)tt * 64 + n0;
            asm volatile("red.global.add.v4.f32 [%0], {%1, %2, %3, %4};"
                         :: "l"(p), "f"(a0), "f"(a1), "f"(a2), "f"(a3) : "memory");
            asm volatile("red.global.add.v4.f32 [%0], {%1, %2, %3, %4};"
                         :: "l"(p + 4), "f"(a4), "f"(a5), "f"(a6), "f"(a7) : "memory");
        }
        __syncthreads();
    }
}

// ---------------------------------------------------------------------------
// Finalize: z = (S @ WfU)*inv + cB*bscale + ub1; out = silu(z) @ upd_w2 + ub2
// GEMV1 from constant (LDCU), GEMV2 from shared (LDS).
// ---------------------------------------------------------------------------
__global__ __launch_bounds__(128, 4) void final_kernel(
    const float* __restrict__ upd_w2, float* __restrict__ out, int G) {
    __shared__ ulonglong2 sU2[HD * 16];
    for (int i = threadIdx.x; i < HD * 16; i += blockDim.x)
        sU2[i] = reinterpret_cast<const ulonglong2*>(upd_w2)[i];
    __syncthreads();

    for (int g = blockIdx.x * blockDim.x + threadIdx.x; g < G;
         g += gridDim.x * blockDim.x) {
        float cnt = g_cnt[g];
        float inv = __fdividef(1.0f, fmaxf(cnt, 1.0f));
        float bscale = cnt * inv;
        const float4* Srow = reinterpret_cast<const float4*>(g_sums + (size_t)g * 64);

        float vz[64];
#pragma unroll 1
        for (int h = 0; h < 2; h++) {
            unsigned long long acc[16];
#pragma unroll
            for (int p = 0; p < 16; p++) acc[p] = 0ULL;
#pragma unroll 2
            for (int k4 = 0; k4 < 16; k4++) {
                float4 sv = Srow[k4];
                float xs[4] = {sv.x, sv.y, sv.z, sv.w};
#pragma unroll
                for (int kk = 0; kk < 4; kk++) {
                    int k = 4 * k4 + kk;
                    unsigned long long vp = bcast2(xs[kk]);
#pragma unroll
                    for (int q = 0; q < 8; q++) {
                        ulonglong2 w = ldc128(c_WfU + k * 64 + h * 32 + 4 * q);
                        fma2(acc[2 * q], vp, w.x);
                        fma2(acc[2 * q + 1], vp, w.y);
                    }
                }
            }
#pragma unroll
            for (int p = 0; p < 16; p++) {
                float a, b;
                unpack2(acc[p], a, b);
                int j = h * 32 + 2 * p;
                vz[j] = silu_f(fmaf(a, inv, fmaf(c_cB[j], bscale, c_ub1[j])));
                vz[j + 1] =
                    silu_f(fmaf(b, inv, fmaf(c_cB[j + 1], bscale, c_ub1[j + 1])));
            }
        }

        float4* orow = reinterpret_cast<float4*>(out + (size_t)g * 64);
#pragma unroll 1
        for (int h = 0; h < 2; h++) {
            unsigned long long acc[16];
#pragma unroll
            for (int p = 0; p < 16; p++) acc[p] = ldc64(c_ub2 + h * 32 + 2 * p);
#pragma unroll 4
            for (int k = 0; k < 64; k++) {
                unsigned long long vp = bcast2(vz[k]);
                const ulonglong2* wr = sU2 + k * 16 + h * 8;
#pragma unroll
                for (int q = 0; q < 8; q++) {
                    ulonglong2 w = wr[q];
                    fma2(acc[2 * q], vp, w.x);
                    fma2(acc[2 * q + 1], vp, w.y);
                }
            }
#pragma unroll
            for (int p = 0; p < 8; p++) {
                float a0, a1, a2, a3;
                unpack2(acc[2 * p], a0, a1);
                unpack2(acc[2 * p + 1], a2, a3);
                orow[h * 8 + p] = make_float4(a0, a1, a2, a3);
            }
        }
    }
}

// ---------------------------------------------------------------------------
extern "C" void kernel_launch(void* const* d_in, const int* in_sizes, int n_in,
                              void* d_out, int out_size) {
    const float* node_features = (const float*)d_in[0];
    const float* node_pos      = (const float*)d_in[1];
    const float* grid_pos      = (const float*)d_in[2];
    const float* orientations  = (const float*)d_in[3];
    const int*   edge_index    = (const int*)d_in[4];
    const float* node_w1 = (const float*)d_in[5];
    const float* node_b1 = (const float*)d_in[6];
    const float* node_w2 = (const float*)d_in[7];
    const float* node_b2 = (const float*)d_in[8];
    const float* edge_w1 = (const float*)d_in[9];
    const float* edge_b1 = (const float*)d_in[10];
    const float* edge_w2 = (const float*)d_in[11];
    const float* edge_b2 = (const float*)d_in[12];
    const float* msg_w1  = (const float*)d_in[13];
    const float* msg_b1  = (const float*)d_in[14];
    const float* msg_w2  = (const float*)d_in[15];
    const float* msg_b2  = (const float*)d_in[16];
    const float* upd_w1  = (const float*)d_in[17];
    const float* upd_b1  = (const float*)d_in[18];
    const float* upd_w2  = (const float*)d_in[19];
    const float* upd_b2  = (const float*)d_in[20];

    int N = in_sizes[0] / 64;
    int G = in_sizes[2] / 3;
    int E = in_sizes[4] / 2;
    const int* src = edge_index;
    const int* tgt = edge_index + E;

    cudaStream_t stream = 0;  // harness captures the legacy default stream

    cudaFuncSetAttribute(edge_kernel, cudaFuncAttributeMaxDynamicSharedMemorySize,
                         EDGE_SMEM);

    // host-side symbol address lookups (capture-invisible)
    void *pWfU, *pcA, *pcB, *pSums, *pCnt;
    cudaGetSymbolAddress(&pWfU, g_WfU);
    cudaGetSymbolAddress(&pcA, g_cA);
    cudaGetSymbolAddress(&pcB, g_cB);
    cudaGetSymbolAddress(&pSums, g_sums);
    cudaGetSymbolAddress(&pCnt, g_cnt);

    // device-side folds
    fold_kernel<<<64, 192, 0, stream>>>(node_w2, edge_w2, msg_w1, msg_w2, upd_w1);
    bias_kernel<<<1, 128, 0, stream>>>(node_b2, edge_b2, msg_w1, msg_b1, msg_b2,
                                       upd_w1);

    // stage uniform weights into constant memory (all D2D async, capturable)
    cudaMemcpyToSymbolAsync(c_W1, node_w1, HD * HD * 4, 0,
                            cudaMemcpyDeviceToDevice, stream);
    cudaMemcpyToSymbolAsync(c_ew, edge_w1, 6 * HD * 4, 0,
                            cudaMemcpyDeviceToDevice, stream);
    cudaMemcpyToSymbolAsync(c_eb1, edge_b1, HD * 4, 0,
                            cudaMemcpyDeviceToDevice, stream);
    cudaMemcpyToSymbolAsync(c_nb1, node_b1, HD * 4, 0,
                            cudaMemcpyDeviceToDevice, stream);
    cudaMemcpyToSymbolAsync(c_ub1, upd_b1, HD * 4, 0,
                            cudaMemcpyDeviceToDevice, stream);
    cudaMemcpyToSymbolAsync(c_ub2, upd_b2, HD * 4, 0,
                            cudaMemcpyDeviceToDevice, stream);
    cudaMemcpyToSymbolAsync(c_WfU, pWfU, HD * HD * 4, 0,
                            cudaMemcpyDeviceToDevice, stream);
    cudaMemcpyToSymbolAsync(c_cA, pcA, HD * 4, 0,
                            cudaMemcpyDeviceToDevice, stream);
    cudaMemcpyToSymbolAsync(c_cB, pcB, HD * 4, 0,
                            cudaMemcpyDeviceToDevice, stream);

    // zero scatter buffers
    cudaMemsetAsync(pSums, 0, (size_t)G * HD * 4, stream);
    cudaMemsetAsync(pCnt, 0, (size_t)G * 4, stream);

    node_kernel<<<(N + 127) / 128, 128, 0, stream>>>(node_features, N);
    int numTiles = (E + EDGE_TILE - 1) / EDGE_TILE;
    int nb = numTiles < 592 ? numTiles : 592;
    edge_kernel<<<nb, 128, EDGE_SMEM, stream>>>(src, tgt, node_pos, grid_pos,
                                                orientations, E, G);
    final_kernel<<<(G + 127) / 128, 128, 0, stream>>>(upd_w2, (float*)d_out, G);
}

// round 11
// speedup vs baseline: 4.4321x; 1.1483x over previous
#include <cuda_runtime.h>

#define HD 64
#define NMAX 100000
#define GMAX 32768

// Scratch (no allocations allowed -> __device__ globals)
__device__ __align__(16) float g_A[NMAX * HD];    // cA + silu(n1) @ Wf2
__device__ __align__(16) float g_PR[NMAX * 12];   // packed [pos(3) | R(9)] per node
__device__ __align__(16) float g_GP[GMAX * 4];    // padded grid_pos
__device__ __align__(16) float g_Wf[HD * HD];     // edge_w2 @ msg_w1[64:128]
__device__ __align__(16) float g_Wf2[HD * HD];    // node_w2 @ msg_w1[0:64]
__device__ __align__(16) float g_sums[GMAX * HD];
__device__ float g_cnt[GMAX];

struct CParams {
    float WfU[HD * HD];  // msg_w2 @ upd_w1
    float cA[HD];        // msg_b1 + node_b2@msg_w1_top + edge_b2@msg_w1_bot
    float cB[HD];        // msg_b2 @ upd_w1
    float eb1[HD];
    float nb1[HD];
    float ub1[HD];
    float ub2[HD];
};
__device__ __align__(16) CParams g_P;     // staging
__constant__ __align__(16) CParams c_P;   // uniform-access copy
__constant__ __align__(16) float c_W1[HD * HD];  // node_w1
__constant__ __align__(16) float c_ew[6 * HD];   // edge_w1 (6x64)

__device__ __forceinline__ float silu_f(float x) {
    return __fdividef(x, 1.0f + __expf(-x));
}
__device__ __forceinline__ float silu_t(float x) {  // tanh.approx (1 MUFU)
    float h = 0.5f * x, t;
    asm("tanh.approx.f32 %0, %1;" : "=f"(t) : "f"(h));
    return fmaf(h, t, h);
}
__device__ __forceinline__ unsigned long long pack2(float x, float y) {
    unsigned long long r;
    asm("mov.b64 %0, {%1, %2};" : "=l"(r) : "f"(x), "f"(y));
    return r;
}
__device__ __forceinline__ void unpack2(unsigned long long v, float& x, float& y) {
    asm("mov.b64 {%0, %1}, %2;" : "=f"(x), "=f"(y) : "l"(v));
}
__device__ __forceinline__ unsigned long long bcast2(float x) {
    unsigned long long r;
    asm("mov.b64 %0, {%1, %1};" : "=l"(r) : "f"(x));
    return r;
}
__device__ __forceinline__ void fma2(unsigned long long& acc, unsigned long long a,
                                     unsigned long long b) {
    asm("fma.rn.f32x2 %0, %1, %2, %0;" : "+l"(acc) : "l"(a), "l"(b));
}
__device__ __forceinline__ unsigned long long ldc64(const float* p) {
    return *reinterpret_cast<const unsigned long long*>(p);
}
__device__ __forceinline__ ulonglong2 ldc128(const float* p) {
    return *reinterpret_cast<const ulonglong2*>(p);
}

// ---------------------------------------------------------------------------
// prep_kernel: blocks 0..63  -> weight folds (row i = blockIdx.x)
//              block 64      -> biases + small-vector staging into g_P
//              blocks 65..   -> pack g_PR (nodes) and g_GP (grid)
// ---------------------------------------------------------------------------
__global__ void prep_kernel(const float* __restrict__ node_w2,
                            const float* __restrict__ edge_w2,
                            const float* __restrict__ msg_w1,
                            const float* __restrict__ msg_w2,
                            const float* __restrict__ upd_w1,
                            const float* __restrict__ node_b2,
                            const float* __restrict__ edge_b2,
                            const float* __restrict__ msg_b1,
                            const float* __restrict__ msg_b2,
                            const float* __restrict__ node_b1,
                            const float* __restrict__ edge_b1,
                            const float* __restrict__ upd_b1,
                            const float* __restrict__ upd_b2,
                            const float* __restrict__ node_pos,
                            const float* __restrict__ orient,
                            const float* __restrict__ grid_pos,
                            int N, int G) {
    int b = blockIdx.x;
    if (b < 64) {  // folds: output row i = b
        int i = b;
        int j = threadIdx.x & 63;
        int which = threadIdx.x >> 6;  // 0..2 (192 threads)
        float a = 0.f;
        if (which == 0) {
            for (int k = 0; k < 64; k++)
                a = fmaf(__ldg(node_w2 + i * 64 + k), __ldg(msg_w1 + k * 64 + j), a);
            g_Wf2[i * 64 + j] = a;
        } else if (which == 1) {
            for (int k = 0; k < 64; k++)
                a = fmaf(__ldg(edge_w2 + i * 64 + k),
                         __ldg(msg_w1 + (64 + k) * 64 + j), a);
            g_Wf[i * 64 + j] = a;
        } else {
            for (int k = 0; k < 64; k++)
                a = fmaf(__ldg(msg_w2 + i * 64 + k), __ldg(upd_w1 + k * 64 + j), a);
            g_P.WfU[i * 64 + j] = a;
        }
        return;
    }
    if (b == 64) {  // biases + staging
        int j = threadIdx.x & 63;
        int which = threadIdx.x >> 6;
        if (which == 0) {
            float c = msg_b1[j];
            for (int k = 0; k < 64; k++) {
                c = fmaf(node_b2[k], msg_w1[k * 64 + j], c);
                c = fmaf(edge_b2[k], msg_w1[(64 + k) * 64 + j], c);
            }
            g_P.cA[j] = c;
            g_P.eb1[j] = edge_b1[j];
            g_P.nb1[j] = node_b1[j];
        } else if (which == 1) {
            float c = 0.f;
            for (int k = 0; k < 64; k++)
                c = fmaf(msg_b2[k], upd_w1[k * 64 + j], c);
            g_P.cB[j] = c;
            g_P.ub1[j] = upd_b1[j];
            g_P.ub2[j] = upd_b2[j];
        }
        return;
    }
    // packing
    int idx = (b - 65) * blockDim.x + threadIdx.x;
    if (idx < N) {
        const float* pp = node_pos + idx * 3;
        const float* rr = orient + (size_t)idx * 9;
        float4* dst = reinterpret_cast<float4*>(g_PR + (size_t)idx * 12);
        dst[0] = make_float4(pp[0], pp[1], pp[2], rr[0]);
        dst[1] = make_float4(rr[1], rr[2], rr[3], rr[4]);
        dst[2] = make_float4(rr[5], rr[6], rr[7], rr[8]);
    } else if (idx - N < G) {
        int g = idx - N;
        reinterpret_cast<float4*>(g_GP)[g] =
            make_float4(grid_pos[g * 3], grid_pos[g * 3 + 1], grid_pos[g * 3 + 2],
                        0.f);
    }
}

// ---------------------------------------------------------------------------
// Per-node: A'[n] = cA + silu(x @ c_W1 + nb1) @ Wf2
// GEMV1 reads constant (uniform port), GEMV2 reads shared -> two ports.
// ---------------------------------------------------------------------------
__global__ __launch_bounds__(128, 4) void node_kernel(
    const float* __restrict__ x, int N) {
    __shared__ ulonglong2 sWf2[HD * 16];
    for (int i = threadIdx.x; i < HD * 16; i += blockDim.x)
        sWf2[i] = reinterpret_cast<const ulonglong2*>(g_Wf2)[i];
    __syncthreads();

    for (int n = blockIdx.x * blockDim.x + threadIdx.x; n < N;
         n += gridDim.x * blockDim.x) {
        const float4* xr = reinterpret_cast<const float4*>(x + (size_t)n * 64);
        float v[64];
#pragma unroll 1
        for (int h = 0; h < 2; h++) {
            unsigned long long acc[16];
#pragma unroll
            for (int p = 0; p < 16; p++) acc[p] = ldc64(c_P.nb1 + h * 32 + 2 * p);
#pragma unroll 2
            for (int k4 = 0; k4 < 16; k4++) {
                float4 xv = __ldg(xr + k4);
                float xs[4] = {xv.x, xv.y, xv.z, xv.w};
#pragma unroll
                for (int kk = 0; kk < 4; kk++) {
                    int k = 4 * k4 + kk;
                    unsigned long long vp = bcast2(xs[kk]);
#pragma unroll
                    for (int q = 0; q < 8; q++) {
                        ulonglong2 w = ldc128(c_W1 + k * 64 + h * 32 + 4 * q);
                        fma2(acc[2 * q], vp, w.x);
                        fma2(acc[2 * q + 1], vp, w.y);
                    }
                }
            }
#pragma unroll
            for (int p = 0; p < 16; p++) {
                float a, b;
                unpack2(acc[p], a, b);
                v[h * 32 + 2 * p] = silu_f(a);
                v[h * 32 + 2 * p + 1] = silu_f(b);
            }
        }
        float4* Arow = reinterpret_cast<float4*>(g_A + (size_t)n * 64);
#pragma unroll 1
        for (int h = 0; h < 2; h++) {
            unsigned long long acc[16];
#pragma unroll
            for (int p = 0; p < 16; p++) acc[p] = ldc64(c_P.cA + h * 32 + 2 * p);
#pragma unroll 4
            for (int k = 0; k < 64; k++) {
                unsigned long long vp = bcast2(v[k]);
                const ulonglong2* wr = sWf2 + k * 16 + h * 8;
#pragma unroll
                for (int q = 0; q < 8; q++) {
                    ulonglong2 w = wr[q];
                    fma2(acc[2 * q], vp, w.x);
                    fma2(acc[2 * q + 1], vp, w.y);
                }
            }
#pragma unroll
            for (int p = 0; p < 8; p++) {
                float a0, a1, a2, a3;
                unpack2(acc[2 * p], a0, a1);
                unpack2(acc[2 * p + 1], a2, a3);
                Arow[h * 8 + p] = make_float4(a0, a1, a2, a3);
            }
        }
    }
}

// ---------------------------------------------------------------------------
// Edge kernel (tile-GEMM). Phase A uses packed float4 gathers (g_PR, g_GP).
// ---------------------------------------------------------------------------
#define EDGE_TILE 128
#define EDGE_SMEM (32768 + 16384 + 512 + 512)

__global__ __launch_bounds__(128, 4) void edge_kernel(
    const int* __restrict__ src, const int* __restrict__ tgt, int E, int G) {
    extern __shared__ char smem[];
    float4* vT4 = reinterpret_cast<float4*>(smem);                  // [64][128] f
    float* vTf = reinterpret_cast<float*>(smem);
    ulonglong2* sWf = reinterpret_cast<ulonglong2*>(smem + 32768);  // [64][16]
    int* s_sidx = reinterpret_cast<int*>(smem + 32768 + 16384);     // 128
    int* s_tidx = s_sidx + 128;                                     // 128

    const int tid = threadIdx.x;
    for (int i = tid; i < HD * 16; i += blockDim.x)
        sWf[i] = reinterpret_cast<const ulonglong2*>(g_Wf)[i];
    __syncthreads();

    const int m0 = (tid >> 3) << 3;
    const int n0 = (tid & 7) << 3;

    int numTiles = (E + EDGE_TILE - 1) / EDGE_TILE;
    for (int tile = blockIdx.x; tile < numTiles; tile += gridDim.x) {
        int e = tile * EDGE_TILE + tid;

        // ---- Phase A ----
        int s = 0, t = -1;
        if (e < E) {
            s = src[e];
            int tt = tgt[e];
            if (tt >= 0 && tt < G) t = tt;
        }
        bool val = (t >= 0);
        const float4* PR = reinterpret_cast<const float4*>(g_PR + (size_t)s * 12);
        float4 p0 = __ldg(PR), p1 = __ldg(PR + 1), p2 = __ldg(PR + 2);
        float t0 = 0.f, t1 = 0.f, t2 = 0.f;
        if (val) {
            float4 g4 = __ldg(reinterpret_cast<const float4*>(g_GP) + t);
            float rx = g4.x - p0.x, ry = g4.y - p0.y, rz = g4.z - p0.z;
            // R row-major: R00=p0.w R01=p1.x R02=p1.y R10=p1.z R11=p1.w
            //              R12=p2.x R20=p2.y R21=p2.z R22=p2.w
            t0 = rx * p0.w + ry * p1.z + rz * p2.y;
            t1 = rx * p1.x + ry * p1.w + rz * p2.z;
            t2 = rx * p1.y + ry * p2.x + rz * p2.w;
        }
        {
            unsigned long long bp0 = bcast2(p0.x), bp1 = bcast2(p0.y),
                               bp2 = bcast2(p0.z);
            unsigned long long bt0 = bcast2(t0), bt1 = bcast2(t1), bt2 = bcast2(t2);
            float* col = vTf + tid;
#pragma unroll
            for (int p = 0; p < 32; p++) {
                unsigned long long a = ldc64(c_P.eb1 + 2 * p);
                fma2(a, bp0, ldc64(c_ew + 0 * 64 + 2 * p));
                fma2(a, bp1, ldc64(c_ew + 1 * 64 + 2 * p));
                fma2(a, bp2, ldc64(c_ew + 2 * 64 + 2 * p));
                fma2(a, bt0, ldc64(c_ew + 3 * 64 + 2 * p));
                fma2(a, bt1, ldc64(c_ew + 4 * 64 + 2 * p));
                fma2(a, bt2, ldc64(c_ew + 5 * 64 + 2 * p));
                float x0, x1;
                unpack2(a, x0, x1);
                col[(2 * p) * 128] = val ? silu_t(x0) : 0.f;
                col[(2 * p + 1) * 128] = val ? silu_t(x1) : 0.f;
            }
        }
        s_sidx[tid] = s;
        s_tidx[tid] = t;
        if (val) atomicAdd(&g_cnt[t], 1.0f);
        __syncthreads();

        // ---- Phase B: 128x64x64 GEMM ----
        unsigned long long acc[32];
#pragma unroll
        for (int i = 0; i < 32; i++) acc[i] = 0ULL;
#pragma unroll 4
        for (int k = 0; k < 64; k++) {
            float4 a0 = vT4[k * 32 + (m0 >> 2)];
            float4 a1 = vT4[k * 32 + (m0 >> 2) + 1];
            ulonglong2 w0 = sWf[k * 16 + (n0 >> 2)];
            ulonglong2 w1 = sWf[k * 16 + (n0 >> 2) + 1];
            float av[8] = {a0.x, a0.y, a0.z, a0.w, a1.x, a1.y, a1.z, a1.w};
#pragma unroll
            for (int mi = 0; mi < 8; mi++) {
                unsigned long long ap = bcast2(av[mi]);
                fma2(acc[mi * 4 + 0], ap, w0.x);
                fma2(acc[mi * 4 + 1], ap, w0.y);
                fma2(acc[mi * 4 + 2], ap, w1.x);
                fma2(acc[mi * 4 + 3], ap, w1.y);
            }
        }

        // ---- Phase C: + A'[s], silu, scatter ----
#pragma unroll
        for (int mi = 0; mi < 8; mi++) {
            int m = m0 + mi;
            int tt = s_tidx[m];
            if (tt < 0) continue;
            int ss = s_sidx[m];
            const float4* Ar =
                reinterpret_cast<const float4*>(g_A + (size_t)ss * 64 + n0);
            float4 b0 = __ldg(Ar), b1 = __ldg(Ar + 1);
            float a0, a1, a2, a3, a4, a5, a6, a7;
            unpack2(acc[mi * 4 + 0], a0, a1);
            unpack2(acc[mi * 4 + 1], a2, a3);
            unpack2(acc[mi * 4 + 2], a4, a5);
            unpack2(acc[mi * 4 + 3], a6, a7);
            a0 = silu_t(a0 + b0.x); a1 = silu_t(a1 + b0.y);
            a2 = silu_t(a2 + b0.z); a3 = silu_t(a3 + b0.w);
            a4 = silu_t(a4 + b1.x); a5 = silu_t(a5 + b1.y);
            a6 = silu_t(a6 + b1.z); a7 = silu_t(a7 + b1.w);
            float* p = g_sums + (size_t)tt * 64 + n0;
            asm volatile("red.global.add.v4.f32 [%0], {%1, %2, %3, %4};"
                         :: "l"(p), "f"(a0), "f"(a1), "f"(a2), "f"(a3) : "memory");
            asm volatile("red.global.add.v4.f32 [%0], {%1, %2, %3, %4};"
                         :: "l"(p + 4), "f"(a4), "f"(a5), "f"(a6), "f"(a7) : "memory");
        }
        __syncthreads();
    }
}

// ---------------------------------------------------------------------------
// Finalize: z = (S @ WfU)*inv + cB*bscale + ub1; out = silu(z) @ upd_w2 + ub2
// ---------------------------------------------------------------------------
__global__ __launch_bounds__(128, 4) void final_kernel(
    const float* __restrict__ upd_w2, float* __restrict__ out, int G) {
    __shared__ ulonglong2 sU2[HD * 16];
    for (int i = threadIdx.x; i < HD * 16; i += blockDim.x)
        sU2[i] = reinterpret_cast<const ulonglong2*>(upd_w2)[i];
    __syncthreads();

    for (int g = blockIdx.x * blockDim.x + threadIdx.x; g < G;
         g += gridDim.x * blockDim.x) {
        float cnt = g_cnt[g];
        float inv = __fdividef(1.0f, fmaxf(cnt, 1.0f));
        float bscale = cnt * inv;
        const float4* Srow = reinterpret_cast<const float4*>(g_sums + (size_t)g * 64);

        float vz[64];
#pragma unroll 1
        for (int h = 0; h < 2; h++) {
            unsigned long long acc[16];
#pragma unroll
            for (int p = 0; p < 16; p++) acc[p] = 0ULL;
#pragma unroll 2
            for (int k4 = 0; k4 < 16; k4++) {
                float4 sv = Srow[k4];
                float xs[4] = {sv.x, sv.y, sv.z, sv.w};
#pragma unroll
                for (int kk = 0; kk < 4; kk++) {
                    int k = 4 * k4 + kk;
                    unsigned long long vp = bcast2(xs[kk]);
#pragma unroll
                    for (int q = 0; q < 8; q++) {
                        ulonglong2 w = ldc128(c_P.WfU + k * 64 + h * 32 + 4 * q);
                        fma2(acc[2 * q], vp, w.x);
                        fma2(acc[2 * q + 1], vp, w.y);
                    }
                }
            }
#pragma unroll
            for (int p = 0; p < 16; p++) {
                float a, b;
                unpack2(acc[p], a, b);
                int j = h * 32 + 2 * p;
                vz[j] = silu_f(fmaf(a, inv, fmaf(c_P.cB[j], bscale, c_P.ub1[j])));
                vz[j + 1] = silu_f(
                    fmaf(b, inv, fmaf(c_P.cB[j + 1], bscale, c_P.ub1[j + 1])));
            }
        }

        float4* orow = reinterpret_cast<float4*>(out + (size_t)g * 64);
#pragma unroll 1
        for (int h = 0; h < 2; h++) {
            unsigned long long acc[16];
#pragma unroll
            for (int p = 0; p < 16; p++) acc[p] = ldc64(c_P.ub2 + h * 32 + 2 * p);
#pragma unroll 4
            for (int k = 0; k < 64; k++) {
                unsigned long long vp = bcast2(vz[k]);
                const ulonglong2* wr = sU2 + k * 16 + h * 8;
#pragma unroll
                for (int q = 0; q < 8; q++) {
                    ulonglong2 w = wr[q];
                    fma2(acc[2 * q], vp, w.x);
                    fma2(acc[2 * q + 1], vp, w.y);
                }
            }
#pragma unroll
            for (int p = 0; p < 8; p++) {
                float a0, a1, a2, a3;
                unpack2(acc[2 * p], a0, a1);
                unpack2(acc[2 * p + 1], a2, a3);
                orow[h * 8 + p] = make_float4(a0, a1, a2, a3);
            }
        }
    }
}

// ---------------------------------------------------------------------------
extern "C" void kernel_launch(void* const* d_in, const int* in_sizes, int n_in,
                              void* d_out, int out_size) {
    const float* node_features = (const float*)d_in[0];
    const float* node_pos      = (const float*)d_in[1];
    const float* grid_pos      = (const float*)d_in[2];
    const float* orientations  = (const float*)d_in[3];
    const int*   edge_index    = (const int*)d_in[4];
    const float* node_w1 = (const float*)d_in[5];
    const float* node_b1 = (const float*)d_in[6];
    const float* node_w2 = (const float*)d_in[7];
    const float* node_b2 = (const float*)d_in[8];
    const float* edge_w1 = (const float*)d_in[9];
    const float* edge_b1 = (const float*)d_in[10];
    const float* edge_w2 = (const float*)d_in[11];
    const float* edge_b2 = (const float*)d_in[12];
    const float* msg_w1  = (const float*)d_in[13];
    const float* msg_b1  = (const float*)d_in[14];
    const float* msg_w2  = (const float*)d_in[15];
    const float* msg_b2  = (const float*)d_in[16];
    const float* upd_w1  = (const float*)d_in[17];
    const float* upd_b1  = (const float*)d_in[18];
    const float* upd_w2  = (const float*)d_in[19];
    const float* upd_b2  = (const float*)d_in[20];

    int N = in_sizes[0] / 64;
    int G = in_sizes[2] / 3;
    int E = in_sizes[4] / 2;
    const int* src = edge_index;
    const int* tgt = edge_index + E;

    cudaStream_t stream = 0;

    cudaFuncSetAttribute(edge_kernel, cudaFuncAttributeMaxDynamicSharedMemorySize,
                         EDGE_SMEM);

    void *pP, *pSums, *pCnt;
    cudaGetSymbolAddress(&pP, g_P);
    cudaGetSymbolAddress(&pSums, g_sums);
    cudaGetSymbolAddress(&pCnt, g_cnt);

    // prep: folds + biases + packing (blocks 65.. cover N+G items @192 thr)
    int packBlocks = (N + G + 191) / 192;
    prep_kernel<<<65 + packBlocks, 192, 0, stream>>>(
        node_w2, edge_w2, msg_w1, msg_w2, upd_w1, node_b2, edge_b2, msg_b1,
        msg_b2, node_b1, edge_b1, upd_b1, upd_b2, node_pos, orientations,
        grid_pos, N, G);

    // constant staging: 3 copies total
    cudaMemcpyToSymbolAsync(c_P, pP, sizeof(CParams), 0,
                            cudaMemcpyDeviceToDevice, stream);
    cudaMemcpyToSymbolAsync(c_W1, node_w1, HD * HD * 4, 0,
                            cudaMemcpyDeviceToDevice, stream);
    cudaMemcpyToSymbolAsync(c_ew, edge_w1, 6 * HD * 4, 0,
                            cudaMemcpyDeviceToDevice, stream);

    // zero scatter buffers
    cudaMemsetAsync(pSums, 0, (size_t)G * HD * 4, stream);
    cudaMemsetAsync(pCnt, 0, (size_t)G * 4, stream);

    node_kernel<<<(N + 127) / 128, 128, 0, stream>>>(node_features, N);
    int numTiles = (E + EDGE_TILE - 1) / EDGE_TILE;
    int nb = numTiles < 592 ? numTiles : 592;
    edge_kernel<<<nb, 128, EDGE_SMEM, stream>>>(src, tgt, E, G);
    final_kernel<<<(G + 127) / 128, 128, 0, stream>>>(upd_w2, (float*)d_out, G);
}

// round 14
// speedup vs baseline: 5.4931x; 1.2394x over previous
#include <cuda_runtime.h>

#define HD 64
#define NMAX 100000
#define GMAX 32768

// Scratch (no allocations allowed -> __device__ globals)
__device__ __align__(16) float g_A[NMAX * HD];    // cA + silu(n1) @ Wf2
__device__ __align__(16) float g_PR[NMAX * 12];   // packed [pos(3) | R(9)]
__device__ __align__(16) float g_GP[GMAX * 4];    // padded grid_pos
__device__ __align__(16) float g_Wf[HD * HD];     // edge_w2 @ msg_w1[64:128]
__device__ __align__(16) float g_Wf2[HD * HD];    // node_w2 @ msg_w1[0:64]
__device__ __align__(16) float g_WfU[HD * HD];    // msg_w2 @ upd_w1
__device__ __align__(16) float g_sums[GMAX * HD];
__device__ float g_cnt[GMAX];

struct CParams {
    float cA[HD];   // msg_b1 + node_b2@msg_w1_top + edge_b2@msg_w1_bot
    float cB[HD];   // msg_b2 @ upd_w1
    float eb1[HD];
    float nb1[HD];
    float ub1[HD];
    float ub2[HD];
};
__device__ __align__(16) CParams g_P;    // staging
__constant__ __align__(16) CParams c_P;  // uniform-access copy
__constant__ __align__(16) float c_ew[6 * HD];  // edge_w1 (6x64)

__device__ __forceinline__ float silu_t(float x) {  // tanh.approx (1 MUFU)
    float h = 0.5f * x, t;
    asm("tanh.approx.f32 %0, %1;" : "=f"(t) : "f"(h));
    return fmaf(h, t, h);
}
__device__ __forceinline__ unsigned long long pack2(float x, float y) {
    unsigned long long r;
    asm("mov.b64 %0, {%1, %2};" : "=l"(r) : "f"(x), "f"(y));
    return r;
}
__device__ __forceinline__ void unpack2(unsigned long long v, float& x, float& y) {
    asm("mov.b64 {%0, %1}, %2;" : "=f"(x), "=f"(y) : "l"(v));
}
__device__ __forceinline__ unsigned long long bcast2(float x) {
    unsigned long long r;
    asm("mov.b64 %0, {%1, %1};" : "=l"(r) : "f"(x));
    return r;
}
__device__ __forceinline__ void fma2(unsigned long long& acc, unsigned long long a,
                                     unsigned long long b) {
    asm("fma.rn.f32x2 %0, %1, %2, %0;" : "+l"(acc) : "l"(a), "l"(b));
}
__device__ __forceinline__ unsigned long long ldc64(const float* p) {
    return *reinterpret_cast<const unsigned long long*>(p);
}

// Shared 128x64x64 GEMM inner loop: acc (32 x u64) += vT[k][m0..m0+7] * W[k][n0..n0+7]
__device__ __forceinline__ void gemm_tile(const float4* vT4, const ulonglong2* sW,
                                          int m0, int n0,
                                          unsigned long long* acc) {
#pragma unroll 4
    for (int k = 0; k < 64; k++) {
        float4 a0 = vT4[k * 32 + (m0 >> 2)];
        float4 a1 = vT4[k * 32 + (m0 >> 2) + 1];
        ulonglong2 w0 = sW[k * 16 + (n0 >> 2)];
        ulonglong2 w1 = sW[k * 16 + (n0 >> 2) + 1];
        float av[8] = {a0.x, a0.y, a0.z, a0.w, a1.x, a1.y, a1.z, a1.w};
#pragma unroll
        for (int mi = 0; mi < 8; mi++) {
            unsigned long long ap = bcast2(av[mi]);
            fma2(acc[mi * 4 + 0], ap, w0.x);
            fma2(acc[mi * 4 + 1], ap, w0.y);
            fma2(acc[mi * 4 + 2], ap, w1.x);
            fma2(acc[mi * 4 + 3], ap, w1.y);
        }
    }
}

// ---------------------------------------------------------------------------
// prep_kernel: blocks 0..63 -> folds; block 64 -> biases; 65.. -> packing
// ---------------------------------------------------------------------------
__global__ void prep_kernel(const float* __restrict__ node_w2,
                            const float* __restrict__ edge_w2,
                            const float* __restrict__ msg_w1,
                            const float* __restrict__ msg_w2,
                            const float* __restrict__ upd_w1,
                            const float* __restrict__ node_b2,
                            const float* __restrict__ edge_b2,
                            const float* __restrict__ msg_b1,
                            const float* __restrict__ msg_b2,
                            const float* __restrict__ node_b1,
                            const float* __restrict__ edge_b1,
                            const float* __restrict__ upd_b1,
                            const float* __restrict__ upd_b2,
                            const float* __restrict__ node_pos,
                            const float* __restrict__ orient,
                            const float* __restrict__ grid_pos,
                            int N, int G) {
    int b = blockIdx.x;
    if (b < 64) {
        int i = b;
        int j = threadIdx.x & 63;
        int which = threadIdx.x >> 6;
        float a = 0.f;
        if (which == 0) {
            for (int k = 0; k < 64; k++)
                a = fmaf(__ldg(node_w2 + i * 64 + k), __ldg(msg_w1 + k * 64 + j), a);
            g_Wf2[i * 64 + j] = a;
        } else if (which == 1) {
            for (int k = 0; k < 64; k++)
                a = fmaf(__ldg(edge_w2 + i * 64 + k),
                         __ldg(msg_w1 + (64 + k) * 64 + j), a);
            g_Wf[i * 64 + j] = a;
        } else {
            for (int k = 0; k < 64; k++)
                a = fmaf(__ldg(msg_w2 + i * 64 + k), __ldg(upd_w1 + k * 64 + j), a);
            g_WfU[i * 64 + j] = a;
        }
        return;
    }
    if (b == 64) {
        int j = threadIdx.x & 63;
        int which = threadIdx.x >> 6;
        if (which == 0) {
            float c = msg_b1[j];
            for (int k = 0; k < 64; k++) {
                c = fmaf(node_b2[k], msg_w1[k * 64 + j], c);
                c = fmaf(edge_b2[k], msg_w1[(64 + k) * 64 + j], c);
            }
            g_P.cA[j] = c;
            g_P.eb1[j] = edge_b1[j];
            g_P.nb1[j] = node_b1[j];
        } else if (which == 1) {
            float c = 0.f;
            for (int k = 0; k < 64; k++)
                c = fmaf(msg_b2[k], upd_w1[k * 64 + j], c);
            g_P.cB[j] = c;
            g_P.ub1[j] = upd_b1[j];
            g_P.ub2[j] = upd_b2[j];
        }
        return;
    }
    int idx = (b - 65) * blockDim.x + threadIdx.x;
    if (idx < N) {
        const float* pp = node_pos + idx * 3;
        const float* rr = orient + (size_t)idx * 9;
        float4* dst = reinterpret_cast<float4*>(g_PR + (size_t)idx * 12);
        dst[0] = make_float4(pp[0], pp[1], pp[2], rr[0]);
        dst[1] = make_float4(rr[1], rr[2], rr[3], rr[4]);
        dst[2] = make_float4(rr[5], rr[6], rr[7], rr[8]);
    } else if (idx - N < G) {
        int g = idx - N;
        reinterpret_cast<float4*>(g_GP)[g] =
            make_float4(grid_pos[g * 3], grid_pos[g * 3 + 1], grid_pos[g * 3 + 2],
                        0.f);
    }
}

// ---------------------------------------------------------------------------
// node_kernel (tile-GEMM): per 128-node tile,
//   A'[tile] = cA + silu(x_tile @ node_w1 + nb1) @ Wf2
// smem: vT (32KB, reused for z) + sW1 (16KB) + sWf2 (16KB)
// ---------------------------------------------------------------------------
#define NODE_SMEM (32768 + 16384 + 16384)

__global__ __launch_bounds__(128, 3) void node_kernel(
    const float* __restrict__ x, const float* __restrict__ node_w1, int N) {
    extern __shared__ char smem[];
    float* vTf = reinterpret_cast<float*>(smem);
    float4* vT4 = reinterpret_cast<float4*>(smem);
    ulonglong2* sW1 = reinterpret_cast<ulonglong2*>(smem + 32768);
    ulonglong2* sWf2 = reinterpret_cast<ulonglong2*>(smem + 32768 + 16384);

    const int tid = threadIdx.x;
    for (int i = tid; i < HD * 16; i += blockDim.x) {
        sW1[i] = reinterpret_cast<const ulonglong2*>(node_w1)[i];
        sWf2[i] = reinterpret_cast<const ulonglong2*>(g_Wf2)[i];
    }

    const int m0 = (tid >> 3) << 3;
    const int n0 = (tid & 7) << 3;
    int numTiles = (N + 127) / 128;

    for (int tile = blockIdx.x; tile < numTiles; tile += gridDim.x) {
        int item = tile * 128 + tid;
        // Phase A: load x row -> transposed smem column tid
        {
            float* col = vTf + tid;
            if (item < N) {
                const float4* xr =
                    reinterpret_cast<const float4*>(x + (size_t)item * 64);
#pragma unroll
                for (int j4 = 0; j4 < 16; j4++) {
                    float4 xv = __ldg(xr + j4);
                    col[(4 * j4 + 0) * 128] = xv.x;
                    col[(4 * j4 + 1) * 128] = xv.y;
                    col[(4 * j4 + 2) * 128] = xv.z;
                    col[(4 * j4 + 3) * 128] = xv.w;
                }
            } else {
#pragma unroll
                for (int j = 0; j < 64; j++) col[j * 128] = 0.f;
            }
        }
        __syncthreads();

        // GEMM1: z = x @ W1
        unsigned long long acc[32];
#pragma unroll
        for (int i = 0; i < 32; i++) acc[i] = 0ULL;
        gemm_tile(vT4, sW1, m0, n0, acc);
        __syncthreads();  // all GEMM1 reads done before vT overwrite

        // epilogue1: silu(z + nb1) -> transposed store vT[n][m]
#pragma unroll
        for (int mi = 0; mi < 8; mi++) {
            float z[8];
            unpack2(acc[mi * 4 + 0], z[0], z[1]);
            unpack2(acc[mi * 4 + 1], z[2], z[3]);
            unpack2(acc[mi * 4 + 2], z[4], z[5]);
            unpack2(acc[mi * 4 + 3], z[6], z[7]);
#pragma unroll
            for (int ni = 0; ni < 8; ni++)
                vTf[(n0 + ni) * 128 + m0 + mi] = silu_t(z[ni] + c_P.nb1[n0 + ni]);
        }
        __syncthreads();

        // GEMM2: A' = cA + z @ Wf2
#pragma unroll
        for (int i = 0; i < 16; i++) {
            acc[2 * i] = ldc64(c_P.cA + n0 + (i & 3) * 2);
            acc[2 * i + 1] = ldc64(c_P.cA + n0 + 4 + (i & 3) * 2);
        }
        // fix init: acc[mi*4+q] pairs cover n0+2q..; redo cleanly
#pragma unroll
        for (int mi = 0; mi < 8; mi++) {
            acc[mi * 4 + 0] = ldc64(c_P.cA + n0 + 0);
            acc[mi * 4 + 1] = ldc64(c_P.cA + n0 + 2);
            acc[mi * 4 + 2] = ldc64(c_P.cA + n0 + 4);
            acc[mi * 4 + 3] = ldc64(c_P.cA + n0 + 6);
        }
        gemm_tile(vT4, sWf2, m0, n0, acc);

        // write g_A rows
#pragma unroll
        for (int mi = 0; mi < 8; mi++) {
            int m = tile * 128 + m0 + mi;
            if (m >= N) continue;
            float a0, a1, a2, a3, a4, a5, a6, a7;
            unpack2(acc[mi * 4 + 0], a0, a1);
            unpack2(acc[mi * 4 + 1], a2, a3);
            unpack2(acc[mi * 4 + 2], a4, a5);
            unpack2(acc[mi * 4 + 3], a6, a7);
            float4* Arow = reinterpret_cast<float4*>(g_A + (size_t)m * 64 + n0);
            Arow[0] = make_float4(a0, a1, a2, a3);
            Arow[1] = make_float4(a4, a5, a6, a7);
        }
        __syncthreads();
    }
}

// ---------------------------------------------------------------------------
// Edge kernel (tile-GEMM) — unchanged from R11.
// ---------------------------------------------------------------------------
#define EDGE_TILE 128
#define EDGE_SMEM (32768 + 16384 + 512 + 512)

__global__ __launch_bounds__(128, 4) void edge_kernel(
    const int* __restrict__ src, const int* __restrict__ tgt, int E, int G) {
    extern __shared__ char smem[];
    float4* vT4 = reinterpret_cast<float4*>(smem);
    float* vTf = reinterpret_cast<float*>(smem);
    ulonglong2* sWf = reinterpret_cast<ulonglong2*>(smem + 32768);
    int* s_sidx = reinterpret_cast<int*>(smem + 32768 + 16384);
    int* s_tidx = s_sidx + 128;

    const int tid = threadIdx.x;
    for (int i = tid; i < HD * 16; i += blockDim.x)
        sWf[i] = reinterpret_cast<const ulonglong2*>(g_Wf)[i];
    __syncthreads();

    const int m0 = (tid >> 3) << 3;
    const int n0 = (tid & 7) << 3;

    int numTiles = (E + EDGE_TILE - 1) / EDGE_TILE;
    for (int tile = blockIdx.x; tile < numTiles; tile += gridDim.x) {
        int e = tile * EDGE_TILE + tid;

        int s = 0, t = -1;
        if (e < E) {
            s = src[e];
            int tt = tgt[e];
            if (tt >= 0 && tt < G) t = tt;
        }
        bool val = (t >= 0);
        const float4* PR = reinterpret_cast<const float4*>(g_PR + (size_t)s * 12);
        float4 p0 = __ldg(PR), p1 = __ldg(PR + 1), p2 = __ldg(PR + 2);
        float t0 = 0.f, t1 = 0.f, t2 = 0.f;
        if (val) {
            float4 g4 = __ldg(reinterpret_cast<const float4*>(g_GP) + t);
            float rx = g4.x - p0.x, ry = g4.y - p0.y, rz = g4.z - p0.z;
            t0 = rx * p0.w + ry * p1.z + rz * p2.y;
            t1 = rx * p1.x + ry * p1.w + rz * p2.z;
            t2 = rx * p1.y + ry * p2.x + rz * p2.w;
        }
        {
            unsigned long long bp0 = bcast2(p0.x), bp1 = bcast2(p0.y),
                               bp2 = bcast2(p0.z);
            unsigned long long bt0 = bcast2(t0), bt1 = bcast2(t1), bt2 = bcast2(t2);
            float* col = vTf + tid;
#pragma unroll
            for (int p = 0; p < 32; p++) {
                unsigned long long a = ldc64(c_P.eb1 + 2 * p);
                fma2(a, bp0, ldc64(c_ew + 0 * 64 + 2 * p));
                fma2(a, bp1, ldc64(c_ew + 1 * 64 + 2 * p));
                fma2(a, bp2, ldc64(c_ew + 2 * 64 + 2 * p));
                fma2(a, bt0, ldc64(c_ew + 3 * 64 + 2 * p));
                fma2(a, bt1, ldc64(c_ew + 4 * 64 + 2 * p));
                fma2(a, bt2, ldc64(c_ew + 5 * 64 + 2 * p));
                float x0, x1;
                unpack2(a, x0, x1);
                col[(2 * p) * 128] = val ? silu_t(x0) : 0.f;
                col[(2 * p + 1) * 128] = val ? silu_t(x1) : 0.f;
            }
        }
        s_sidx[tid] = s;
        s_tidx[tid] = t;
        if (val) atomicAdd(&g_cnt[t], 1.0f);
        __syncthreads();

        unsigned long long acc[32];
#pragma unroll
        for (int i = 0; i < 32; i++) acc[i] = 0ULL;
        gemm_tile(vT4, sWf, m0, n0, acc);

#pragma unroll
        for (int mi = 0; mi < 8; mi++) {
            int m = m0 + mi;
            int tt = s_tidx[m];
            if (tt < 0) continue;
            int ss = s_sidx[m];
            const float4* Ar =
                reinterpret_cast<const float4*>(g_A + (size_t)ss * 64 + n0);
            float4 b0 = __ldg(Ar), b1 = __ldg(Ar + 1);
            float a0, a1, a2, a3, a4, a5, a6, a7;
            unpack2(acc[mi * 4 + 0], a0, a1);
            unpack2(acc[mi * 4 + 1], a2, a3);
            unpack2(acc[mi * 4 + 2], a4, a5);
            unpack2(acc[mi * 4 + 3], a6, a7);
            a0 = silu_t(a0 + b0.x); a1 = silu_t(a1 + b0.y);
            a2 = silu_t(a2 + b0.z); a3 = silu_t(a3 + b0.w);
            a4 = silu_t(a4 + b1.x); a5 = silu_t(a5 + b1.y);
            a6 = silu_t(a6 + b1.z); a7 = silu_t(a7 + b1.w);
            float* p = g_sums + (size_t)tt * 64 + n0;
            asm volatile("red.global.add.v4.f32 [%0], {%1, %2, %3, %4};"
                         :: "l"(p), "f"(a0), "f"(a1), "f"(a2), "f"(a3) : "memory");
            asm volatile("red.global.add.v4.f32 [%0], {%1, %2, %3, %4};"
                         :: "l"(p + 4), "f"(a4), "f"(a5), "f"(a6), "f"(a7) : "memory");
        }
        __syncthreads();
    }
}

// ---------------------------------------------------------------------------
// final_kernel (tile-GEMM): per 128-cell tile,
//   z = silu((S @ WfU)*inv + cB*bscale + ub1); out = z @ upd_w2 + ub2
// smem: vT (32KB, reused for z) + sWU (16KB) + sU2 (16KB) + cnt (512B)
// ---------------------------------------------------------------------------
#define FIN_SMEM (32768 + 16384 + 16384 + 512)

__global__ __launch_bounds__(128, 3) void final_kernel(
    const float* __restrict__ upd_w2, float* __restrict__ out, int G) {
    extern __shared__ char smem[];
    float* vTf = reinterpret_cast<float*>(smem);
    float4* vT4 = reinterpret_cast<float4*>(smem);
    ulonglong2* sWU = reinterpret_cast<ulonglong2*>(smem + 32768);
    ulonglong2* sU2 = reinterpret_cast<ulonglong2*>(smem + 32768 + 16384);
    float* scnt = reinterpret_cast<float*>(smem + 32768 + 16384 + 16384);

    const int tid = threadIdx.x;
    for (int i = tid; i < HD * 16; i += blockDim.x) {
        sWU[i] = reinterpret_cast<const ulonglong2*>(g_WfU)[i];
        sU2[i] = reinterpret_cast<const ulonglong2*>(upd_w2)[i];
    }

    const int m0 = (tid >> 3) << 3;
    const int n0 = (tid & 7) << 3;
    int numTiles = (G + 127) / 128;

    for (int tile = blockIdx.x; tile < numTiles; tile += gridDim.x) {
        int cell = tile * 128 + tid;
        // Phase A: load S row -> transposed smem column; cnt -> smem
        {
            float* col = vTf + tid;
            if (cell < G) {
                const float4* Sr =
                    reinterpret_cast<const float4*>(g_sums + (size_t)cell * 64);
#pragma unroll
                for (int j4 = 0; j4 < 16; j4++) {
                    float4 sv = __ldg(Sr + j4);
                    col[(4 * j4 + 0) * 128] = sv.x;
                    col[(4 * j4 + 1) * 128] = sv.y;
                    col[(4 * j4 + 2) * 128] = sv.z;
                    col[(4 * j4 + 3) * 128] = sv.w;
                }
                scnt[tid] = g_cnt[cell];
            } else {
#pragma unroll
                for (int j = 0; j < 64; j++) col[j * 128] = 0.f;
                scnt[tid] = 0.f;
            }
        }
        __syncthreads();

        // GEMM1: S @ WfU
        unsigned long long acc[32];
#pragma unroll
        for (int i = 0; i < 32; i++) acc[i] = 0ULL;
        gemm_tile(vT4, sWU, m0, n0, acc);
        __syncthreads();

        // epilogue1: per-m mean scaling + bias + silu -> transposed z store
#pragma unroll
        for (int mi = 0; mi < 8; mi++) {
            float cnt = scnt[m0 + mi];
            float inv = __fdividef(1.0f, fmaxf(cnt, 1.0f));
            float bscale = cnt * inv;
            float z[8];
            unpack2(acc[mi * 4 + 0], z[0], z[1]);
            unpack2(acc[mi * 4 + 1], z[2], z[3]);
            unpack2(acc[mi * 4 + 2], z[4], z[5]);
            unpack2(acc[mi * 4 + 3], z[6], z[7]);
#pragma unroll
            for (int ni = 0; ni < 8; ni++) {
                int j = n0 + ni;
                vTf[j * 128 + m0 + mi] =
                    silu_t(fmaf(z[ni], inv, fmaf(c_P.cB[j], bscale, c_P.ub1[j])));
            }
        }
        __syncthreads();

        // GEMM2: out = ub2 + z @ upd_w2
#pragma unroll
        for (int mi = 0; mi < 8; mi++) {
            acc[mi * 4 + 0] = ldc64(c_P.ub2 + n0 + 0);
            acc[mi * 4 + 1] = ldc64(c_P.ub2 + n0 + 2);
            acc[mi * 4 + 2] = ldc64(c_P.ub2 + n0 + 4);
            acc[mi * 4 + 3] = ldc64(c_P.ub2 + n0 + 6);
        }
        gemm_tile(vT4, sU2, m0, n0, acc);

#pragma unroll
        for (int mi = 0; mi < 8; mi++) {
            int m = tile * 128 + m0 + mi;
            if (m >= G) continue;
            float a0, a1, a2, a3, a4, a5, a6, a7;
            unpack2(acc[mi * 4 + 0], a0, a1);
            unpack2(acc[mi * 4 + 1], a2, a3);
            unpack2(acc[mi * 4 + 2], a4, a5);
            unpack2(acc[mi * 4 + 3], a6, a7);
            float4* orow = reinterpret_cast<float4*>(out + (size_t)m * 64 + n0);
            orow[0] = make_float4(a0, a1, a2, a3);
            orow[1] = make_float4(a4, a5, a6, a7);
        }
        __syncthreads();
    }
}

// ---------------------------------------------------------------------------
extern "C" void kernel_launch(void* const* d_in, const int* in_sizes, int n_in,
                              void* d_out, int out_size) {
    const float* node_features = (const float*)d_in[0];
    const float* node_pos      = (const float*)d_in[1];
    const float* grid_pos      = (const float*)d_in[2];
    const float* orientations  = (const float*)d_in[3];
    const int*   edge_index    = (const int*)d_in[4];
    const float* node_w1 = (const float*)d_in[5];
    const float* node_b1 = (const float*)d_in[6];
    const float* node_w2 = (const float*)d_in[7];
    const float* node_b2 = (const float*)d_in[8];
    const float* edge_w1 = (const float*)d_in[9];
    const float* edge_b1 = (const float*)d_in[10];
    const float* edge_w2 = (const float*)d_in[11];
    const float* edge_b2 = (const float*)d_in[12];
    const float* msg_w1  = (const float*)d_in[13];
    const float* msg_b1  = (const float*)d_in[14];
    const float* msg_w2  = (const float*)d_in[15];
    const float* msg_b2  = (const float*)d_in[16];
    const float* upd_w1  = (const float*)d_in[17];
    const float* upd_b1  = (const float*)d_in[18];
    const float* upd_w2  = (const float*)d_in[19];
    const float* upd_b2  = (const float*)d_in[20];

    int N = in_sizes[0] / 64;
    int G = in_sizes[2] / 3;
    int E = in_sizes[4] / 2;
    const int* src = edge_index;
    const int* tgt = edge_index + E;

    cudaStream_t stream = 0;

    cudaFuncSetAttribute(edge_kernel, cudaFuncAttributeMaxDynamicSharedMemorySize,
                         EDGE_SMEM);
    cudaFuncSetAttribute(node_kernel, cudaFuncAttributeMaxDynamicSharedMemorySize,
                         NODE_SMEM);
    cudaFuncSetAttribute(final_kernel, cudaFuncAttributeMaxDynamicSharedMemorySize,
                         FIN_SMEM);

    void *pP, *pSums, *pCnt;
    cudaGetSymbolAddress(&pP, g_P);
    cudaGetSymbolAddress(&pSums, g_sums);
    cudaGetSymbolAddress(&pCnt, g_cnt);

    int packBlocks = (N + G + 191) / 192;
    prep_kernel<<<65 + packBlocks, 192, 0, stream>>>(
        node_w2, edge_w2, msg_w1, msg_w2, upd_w1, node_b2, edge_b2, msg_b1,
        msg_b2, node_b1, edge_b1, upd_b1, upd_b2, node_pos, orientations,
        grid_pos, N, G);

    cudaMemcpyToSymbolAsync(c_P, pP, sizeof(CParams), 0,
                            cudaMemcpyDeviceToDevice, stream);
    cudaMemcpyToSymbolAsync(c_ew, edge_w1, 6 * HD * 4, 0,
                            cudaMemcpyDeviceToDevice, stream);

    cudaMemsetAsync(pSums, 0, (size_t)G * HD * 4, stream);
    cudaMemsetAsync(pCnt, 0, (size_t)G * 4, stream);

    int nodeTiles = (N + 127) / 128;
    node_kernel<<<nodeTiles, 128, NODE_SMEM, stream>>>(node_features, node_w1, N);

    int numTiles = (E + EDGE_TILE - 1) / EDGE_TILE;
    int nb = numTiles < 592 ? numTiles : 592;
    edge_kernel<<<nb, 128, EDGE_SMEM, stream>>>(src, tgt, E, G);

    int finTiles = (G + 127) / 128;
    final_kernel<<<finTiles, 128, FIN_SMEM, stream>>>(upd_w2, (float*)d_out, G);
}